// round 9
// baseline (speedup 1.0000x reference)
#include <cuda_runtime.h>
#include <cuda_bf16.h>
#include <cstdint>
#include <math.h>

#define Bx 32
#define Dd 256
#define Kk 2048
#define Nn 32768
#define HWp 1024

#define Q_ELEMS   8388608
#define FULL_OUT  8421379
#define TAU       1e-4f

// ---- device scratch (no dynamic allocations allowed) ----
__device__ __nv_bfloat16 g_BhiT[Dd * Kk];   // 1 MB [D][K] normalized hi
__device__ __nv_bfloat16 g_BloT[Dd * Kk];   // 1 MB [D][K] lo
__device__ float g_Ef[Kk * Dd];             // 2 MB [K][D] normalized fp32 (rescue)
__device__ float g_inv[Kk];
__device__ int   g_idx[Nn];
__device__ int   g_hist[Kk];
__device__ float g_part[1024];
__device__ int   g_rcnt;
__device__ int   g_rlist[Nn];

// ======================= PTX helpers (compute_80+ baseline) ================
__device__ __forceinline__ uint32_t smem_u32(const void* p) {
    uint32_t a;
    asm("{ .reg .u64 t; cvta.to.shared.u64 t, %1; cvt.u32.u64 %0, t; }" : "=r"(a) : "l"(p));
    return a;
}
__device__ __forceinline__ void ldsm_x4_t(uint32_t* r, uint32_t addr) {
    asm volatile("ldmatrix.sync.aligned.m8n8.x4.trans.shared.b16 {%0,%1,%2,%3}, [%4];"
        : "=r"(r[0]), "=r"(r[1]), "=r"(r[2]), "=r"(r[3]) : "r"(addr));
}
__device__ __forceinline__ void mma_bf16(float* c, const uint32_t* a, const uint32_t* b) {
    asm("mma.sync.aligned.m16n8k16.row.col.f32.bf16.bf16.f32 "
        "{%0,%1,%2,%3}, {%4,%5,%6,%7}, {%8,%9}, {%0,%1,%2,%3};"
        : "+f"(c[0]), "+f"(c[1]), "+f"(c[2]), "+f"(c[3])
        : "r"(a[0]), "r"(a[1]), "r"(a[2]), "r"(a[3]), "r"(b[0]), "r"(b[1]));
}
__device__ __forceinline__ void cp_async16(uint32_t dst, const void* src) {
    asm volatile("cp.async.cg.shared.global [%0], [%1], 16;" :: "r"(dst), "l"(src) : "memory");
}
#define CP_COMMIT() asm volatile("cp.async.commit_group;" ::: "memory")
#define CP_WAIT0()  asm volatile("cp.async.wait_group 0;" ::: "memory")

__device__ __forceinline__ uint32_t pack_bf16(float a, float b) {
    __nv_bfloat162 t; t.x = __float2bfloat16(a); t.y = __float2bfloat16(b);
    return *reinterpret_cast<uint32_t*>(&t);
}

// ---------------------------------------------------------------------------
// Kernel 1: per-column inverse norms + zero histogram + reset rescue count
// ---------------------------------------------------------------------------
__global__ void k_invnorm(const float* __restrict__ E) {
    int k = blockIdx.x * blockDim.x + threadIdx.x;
    float ss = 0.f;
#pragma unroll 8
    for (int d = 0; d < Dd; ++d) { float v = E[d * Kk + k]; ss = fmaf(v, v, ss); }
    g_inv[k] = 1.0f / fmaxf(sqrtf(ss), 1e-12f);
    g_hist[k] = 0;
    if (k == 0) g_rcnt = 0;
}

// ---------------------------------------------------------------------------
// Kernel 2: codebook prep: E [D,K] -> g_Ef [K][D] fp32 normalized,
//           g_BhiT/g_BloT [D][K] bf16 split
// ---------------------------------------------------------------------------
__global__ __launch_bounds__(256) void k_prepe(const float* __restrict__ E) {
    __shared__ float t[64][65];
    const int tid = threadIdx.x;
    const int k0 = blockIdx.x * 64, d0 = blockIdx.y * 64;
#pragma unroll
    for (int i = 0; i < 16; ++i) {
        int idx = i * 256 + tid, di = idx >> 6, ki = idx & 63;
        t[di][ki] = E[(size_t)(d0 + di) * Kk + k0 + ki] * g_inv[k0 + ki];
    }
    __syncthreads();
    // [K][D] fp32 (rescue table)
#pragma unroll
    for (int i = 0; i < 16; ++i) {
        int idx = i * 256 + tid, ki = idx >> 6, di = idx & 63;
        g_Ef[(size_t)(k0 + ki) * Dd + d0 + di] = t[di][ki];
    }
    // [D][K] bf16 hi/lo, two K at a time
#pragma unroll
    for (int i = 0; i < 8; ++i) {
        int idx = i * 256 + tid;
        int di = idx >> 5;
        int ki = (idx & 31) * 2;
        float v0 = t[di][ki], v1 = t[di][ki + 1];
        __nv_bfloat16 h0 = __float2bfloat16(v0);
        __nv_bfloat16 h1 = __float2bfloat16(v1);
        float l0 = v0 - __bfloat162float(h0);
        float l1 = v1 - __bfloat162float(h1);
        size_t o = (size_t)(d0 + di) * Kk + k0 + ki;
        __nv_bfloat162 hh; hh.x = h0; hh.y = h1;
        __nv_bfloat162 ll; ll.x = __float2bfloat16(l0); ll.y = __float2bfloat16(l1);
        *reinterpret_cast<__nv_bfloat162*>(&g_BhiT[o]) = hh;
        *reinterpret_cast<__nv_bfloat162*>(&g_BloT[o]) = ll;
    }
}

// ---------------------------------------------------------------------------
// Kernel 3: warp-MMA split-3 bf16 GEMM + top-2 argmax.
// CTA: 256 thr / 64 rows. A built in-kernel from raw x (hi+lo, [d][row]
// layout, 64KB); A fragments via ldmatrix.trans. B streamed via cp.async
// double-buffered [k32][n128] stages. 8 warps: wm=wid&1, wn=wid>>1.
// ---------------------------------------------------------------------------
#define SM_ALO 32768
#define SM_B   65536
#define SM_RED 98304
#define SM_TOT 101376

__global__ __launch_bounds__(256, 2) void k_mma_argmax(const float* __restrict__ x) {
    extern __shared__ char sm[];
    const uint32_t sb = smem_u32(sm);
    const int tid = threadIdx.x;
    const int lane = tid & 31;
    const int wid = tid >> 5;
    const int wm = wid & 1, wn = wid >> 1;
    const int rbase = blockIdx.x * 64;
    const int b = rbase >> 10, hw0 = rbase & 1023;
    const int ldr = tid >> 4, ldu = tid & 15;

    // ---- kick off B chunk 0 (ct=0,kc=0) into stage 0 via cp.async ----
#pragma unroll
    for (int j = 0; j < 2; ++j) {
        int r = j * 16 + ldr;
        size_t so = ((size_t)r * Kk) * 2 + (size_t)ldu * 16;
        uint32_t dst = sb + SM_B + r * 256 + ((ldu ^ (r & 7)) << 4);
        cp_async16(dst, (const char*)g_BhiT + so);
        cp_async16(dst + 8192, (const char*)g_BloT + so);
    }
    CP_COMMIT();

    // ---- build A in smem from raw x: thread tid owns feature d = tid ----
    // x[b][d][hw0 + 0..63] are 64 contiguous floats = this CTA's rows at d.
    {
        const float4* xr4 = (const float4*)(x + ((size_t)b * Dd + tid) * HWp + hw0);
#pragma unroll
        for (int c = 0; c < 8; ++c) {
            float4 v0 = xr4[2 * c], v1 = xr4[2 * c + 1];
            float f[8] = {v0.x, v0.y, v0.z, v0.w, v1.x, v1.y, v1.z, v1.w};
            uint32_t hi[4], lo[4];
#pragma unroll
            for (int q = 0; q < 4; ++q) {
                __nv_bfloat16 h0 = __float2bfloat16(f[2 * q]);
                __nv_bfloat16 h1 = __float2bfloat16(f[2 * q + 1]);
                __nv_bfloat162 hh; hh.x = h0; hh.y = h1;
                hi[q] = *reinterpret_cast<uint32_t*>(&hh);
                lo[q] = pack_bf16(f[2 * q] - __bfloat162float(h0),
                                  f[2 * q + 1] - __bfloat162float(h1));
            }
            uint32_t ad = tid * 128 + ((c ^ (tid & 7)) << 4);
            *(uint4*)(sm + ad) = make_uint4(hi[0], hi[1], hi[2], hi[3]);
            *(uint4*)(sm + SM_ALO + ad) = make_uint4(lo[0], lo[1], lo[2], lo[3]);
        }
    }
    CP_WAIT0();
    __syncthreads();

    float c[2][4][4];
#pragma unroll
    for (int mi = 0; mi < 2; ++mi)
#pragma unroll
        for (int j = 0; j < 4; ++j)
#pragma unroll
            for (int q = 0; q < 4; ++q) c[mi][j][q] = 0.f;

    float v1[4], v2[4];
    int   i1[4];
#pragma unroll
    for (int s = 0; s < 4; ++s) { v1[s] = -3.0e38f; v2[s] = -3.0e38f; i1[s] = 0; }

    int stage = 0;
    const int kk = (lane & 7) + ((lane >> 3) & 1) * 8;
    // A trans-ldsm lane mapping (quadrants of the m16k16 fragment):
    const int a_dl = (lane & 7) + ((lane >> 4) & 1) * 8;   // k offset within 16
    const int a_rc = (lane >> 3) & 1;                       // row-chunk (+8 rows)

    for (int cid = 0; cid < 128; ++cid) {
        const int ct = cid >> 3, kc = cid & 7;

        // issue next chunk's cp.async into the other stage
        if (cid < 127) {
            int nct = (cid + 1) >> 3, nkc = (cid + 1) & 7;
#pragma unroll
            for (int j = 0; j < 2; ++j) {
                int r = j * 16 + ldr;
                size_t so = ((size_t)(nkc * 32 + r) * Kk + nct * 128) * 2 + (size_t)ldu * 16;
                uint32_t dst = sb + SM_B + (stage ^ 1) * 16384 + r * 256 + ((ldu ^ (r & 7)) << 4);
                cp_async16(dst, (const char*)g_BhiT + so);
                cp_async16(dst + 8192, (const char*)g_BloT + so);
            }
        }
        CP_COMMIT();

        // ---- two k16 sub-chunks ----
#pragma unroll
        for (int kcs = 0; kcs < 2; ++kcs) {
            uint32_t ah[2][4], al[2][4];
#pragma unroll
            for (int mi = 0; mi < 2; ++mi) {
                int d0 = kc * 32 + kcs * 16 + a_dl;
                int rc = wm * 4 + mi * 2 + a_rc;
                uint32_t aaddr = sb + d0 * 128 + ((rc ^ (d0 & 7)) << 4);
                ldsm_x4_t(ah[mi], aaddr);
                ldsm_x4_t(al[mi], aaddr + SM_ALO);
            }
            uint32_t bh[2][4], bl[2][4];
            const uint32_t bbase = sb + SM_B + stage * 16384 + kcs * 4096;
#pragma unroll
            for (int p = 0; p < 2; ++p) {
                int u0 = wn * 4 + p * 2 + (lane >> 4);
                uint32_t baddr = bbase + kk * 256 + ((u0 ^ (kk & 7)) << 4);
                ldsm_x4_t(bh[p], baddr);
                ldsm_x4_t(bl[p], baddr + 8192);
            }
            // ---- 24 HMMA: hi*hi + hi*lo + lo*hi ----
#pragma unroll
            for (int mi = 0; mi < 2; ++mi)
#pragma unroll
                for (int p = 0; p < 2; ++p) {
                    mma_bf16(c[mi][2 * p],     ah[mi], &bh[p][0]);
                    mma_bf16(c[mi][2 * p + 1], ah[mi], &bh[p][2]);
                    mma_bf16(c[mi][2 * p],     ah[mi], &bl[p][0]);
                    mma_bf16(c[mi][2 * p + 1], ah[mi], &bl[p][2]);
                    mma_bf16(c[mi][2 * p],     al[mi], &bh[p][0]);
                    mma_bf16(c[mi][2 * p + 1], al[mi], &bh[p][2]);
                }
        }

        // ---- column-tile epilogue: fold accumulators into running top-2 ----
        if (kc == 7) {
            const int cb = ct * 128 + wn * 32 + (lane & 3) * 2;
#pragma unroll
            for (int mi = 0; mi < 2; ++mi)
#pragma unroll
                for (int j = 0; j < 4; ++j)
#pragma unroll
                    for (int q = 0; q < 4; ++q) {
                        float v = c[mi][j][q];
                        int col = cb + j * 8 + (q & 1);
                        int slot = mi * 2 + (q >> 1);
                        if (v > v1[slot]) { v2[slot] = v1[slot]; v1[slot] = v; i1[slot] = col; }
                        else if (v > v2[slot]) { v2[slot] = v; }
                        c[mi][j][q] = 0.f;
                    }
        }

        CP_WAIT0();
        __syncthreads();
        stage ^= 1;
    }

    // ---- cross-lane merge over the 4 lanes sharing a row ----
#pragma unroll
    for (int s = 0; s < 4; ++s) {
#pragma unroll
        for (int m = 1; m <= 2; m <<= 1) {
            float ov1 = __shfl_xor_sync(0xffffffffu, v1[s], m);
            float ov2 = __shfl_xor_sync(0xffffffffu, v2[s], m);
            int   oi1 = __shfl_xor_sync(0xffffffffu, i1[s], m);
            if (ov1 > v1[s]) { v2[s] = fmaxf(v1[s], ov2); v1[s] = ov1; i1[s] = oi1; }
            else             { v2[s] = fmaxf(v2[s], ov1); }
        }
    }
    float* sv1 = (float*)(sm + SM_RED);
    float* sv2 = (float*)(sm + SM_RED + 1024);
    int*   si1 = (int*)  (sm + SM_RED + 2048);
    if ((lane & 3) == 0) {
#pragma unroll
        for (int s = 0; s < 4; ++s) {
            int row = wm * 32 + (s >> 1) * 16 + (s & 1) * 8 + (lane >> 2);
            sv1[row * 4 + wn] = v1[s];
            sv2[row * 4 + wn] = v2[s];
            si1[row * 4 + wn] = i1[s];
        }
    }
    __syncthreads();
    if (tid < 64) {
        float t1 = -3.0e38f, t2 = -3.0e38f;
        int ti = 0;
#pragma unroll
        for (int p = 0; p < 4; ++p) {
            float a1 = sv1[tid * 4 + p], a2 = sv2[tid * 4 + p];
            int ai = si1[tid * 4 + p];
            if (a1 > t1) { t2 = fmaxf(t1, a2); t1 = a1; ti = ai; }
            else         { t2 = fmaxf(t2, a1); }
        }
        g_idx[rbase + tid] = ti;
        if (t1 - t2 < TAU) {
            int p = atomicAdd(&g_rcnt, 1);
            g_rlist[p] = rbase + tid;
        }
    }
}

// ---------------------------------------------------------------------------
// Kernel 4: exact fp32 rescue for rows with small top1-top2 gap.
// ---------------------------------------------------------------------------
__global__ __launch_bounds__(256) void k_rescue(const float* __restrict__ x) {
    __shared__ float sx[8][257];
    __shared__ int   srows[8];
    __shared__ float rv[256];
    __shared__ int   ri[256];
    const int tid = threadIdx.x;
    const int total = g_rcnt;

    for (int t0 = blockIdx.x * 8; t0 < total; t0 += gridDim.x * 8) {
        const int m = min(8, total - t0);
        if (tid < 8) srows[tid] = (tid < m) ? g_rlist[t0 + tid] : 0;
        __syncthreads();
        for (int j = 0; j < 8; ++j) {
            int n = srows[j];
            int b = n >> 10, hw = n & 1023;
            sx[j][tid] = (j < m) ? x[((size_t)b * Dd + tid) * HWp + hw] : 0.f;
        }
        __syncthreads();

        float bv[8]; int bi[8];
#pragma unroll
        for (int j = 0; j < 8; ++j) { bv[j] = -3.0e38f; bi[j] = 0; }
        for (int s = 0; s < 8; ++s) {
            int k = s * 256 + tid;
            const float* er = g_Ef + (size_t)k * Dd;
            float dot[8];
#pragma unroll
            for (int j = 0; j < 8; ++j) dot[j] = 0.f;
            for (int d = 0; d < Dd; d += 4) {
                float4 e = *(const float4*)(er + d);
#pragma unroll
                for (int j = 0; j < 8; ++j) {
                    dot[j] = fmaf(sx[j][d], e.x, dot[j]);
                    dot[j] = fmaf(sx[j][d + 1], e.y, dot[j]);
                    dot[j] = fmaf(sx[j][d + 2], e.z, dot[j]);
                    dot[j] = fmaf(sx[j][d + 3], e.w, dot[j]);
                }
            }
#pragma unroll
            for (int j = 0; j < 8; ++j)
                if (dot[j] > bv[j]) { bv[j] = dot[j]; bi[j] = k; }
        }
        for (int j = 0; j < 8; ++j) {
            rv[tid] = bv[j]; ri[tid] = bi[j];
            __syncthreads();
            for (int s2 = 128; s2 > 0; s2 >>= 1) {
                if (tid < s2) {
                    if (rv[tid + s2] > rv[tid] ||
                        (rv[tid + s2] == rv[tid] && ri[tid + s2] < ri[tid])) {
                        rv[tid] = rv[tid + s2]; ri[tid] = ri[tid + s2];
                    }
                }
                __syncthreads();
            }
            if (tid == 0 && j < m) g_idx[srows[j]] = ri[0];
            __syncthreads();
        }
    }
}

// ---------------------------------------------------------------------------
// Kernel 5: gather + fused MSE partials + histogram + index output (8-way D split)
// ---------------------------------------------------------------------------
__global__ void k_gather(const float* __restrict__ x, const float* __restrict__ E,
                         float* __restrict__ out, int extras) {
    __shared__ float red[256];
    const int tid = threadIdx.x;
    const int n = blockIdx.x * 256 + tid;
    const int q = blockIdx.y;
    const int d0 = q * 32;
    const int idx = g_idx[n];
    const int b = n >> 10;
    const int hw = n & 1023;

    const float* xb = x + ((size_t)b * Dd + d0) * HWp + hw;
    float* ob = out + ((size_t)b * Dd + d0) * HWp + hw;

    float acc = 0.f;
#pragma unroll 4
    for (int d = 0; d < 32; ++d) {
        float qv = E[(d0 + d) * Kk + idx];
        float xv = xb[(size_t)d * HWp];
        ob[(size_t)d * HWp] = qv;
        float df = xv - qv;
        acc = fmaf(df, df, acc);
    }
    if (q == 0) {
        atomicAdd(&g_hist[idx], 1);
        if (extras) out[Q_ELEMS + 3 + n] = (float)idx;
    }

    red[tid] = acc;
    __syncthreads();
    for (int s = 128; s > 0; s >>= 1) {
        if (tid < s) red[tid] += red[tid + s];
        __syncthreads();
    }
    if (tid == 0) g_part[blockIdx.x * 8 + q] = red[0];
}

// ---------------------------------------------------------------------------
// Kernel 6: finalize scalars
// ---------------------------------------------------------------------------
__global__ void k_final(float* __restrict__ out, int extras) {
    __shared__ float red[256];
    const int tid = threadIdx.x;

    red[tid] = g_part[tid] + g_part[tid + 256] + g_part[tid + 512] + g_part[tid + 768];
    __syncthreads();
    for (int s = 128; s > 0; s >>= 1) {
        if (tid < s) red[tid] += red[tid + s];
        __syncthreads();
    }
    float mse = red[0] / (float)Q_ELEMS;
    __syncthreads();

    float e = 0.f;
    for (int bin = tid; bin < Kk; bin += 256) {
        float p = (float)g_hist[bin] / (float)Nn;
        e += p * logf(p + 1e-10f);
    }
    red[tid] = e;
    __syncthreads();
    for (int s = 128; s > 0; s >>= 1) {
        if (tid < s) red[tid] += red[tid + s];
        __syncthreads();
    }
    if (tid == 0 && extras) {
        out[Q_ELEMS + 0] = mse;
        out[Q_ELEMS + 1] = mse;
        out[Q_ELEMS + 2] = red[0];
    }
}

// ---------------------------------------------------------------------------
extern "C" void kernel_launch(void* const* d_in, const int* in_sizes, int n_in,
                              void* d_out, int out_size) {
    const float* x = (const float*)d_in[0];   // [32,256,32,32]
    const float* E = (const float*)d_in[1];   // [256,2048]
    float* out = (float*)d_out;
    const int extras = (out_size >= FULL_OUT) ? 1 : 0;

    k_invnorm<<<Kk / 256, 256>>>(E);
    k_prepe<<<dim3(Kk / 64, Dd / 64), 256>>>(E);

    cudaFuncSetAttribute(k_mma_argmax,
                         cudaFuncAttributeMaxDynamicSharedMemorySize, SM_TOT);
    k_mma_argmax<<<Nn / 64, 256, SM_TOT>>>(x);

    k_rescue<<<128, 256>>>(x);
    k_gather<<<dim3(Nn / 256, 8), 256>>>(x, E, out, extras);
    k_final<<<1, 256>>>(out, extras);
}

// round 10
// speedup vs baseline: 1.5423x; 1.5423x over previous
#include <cuda_runtime.h>
#include <cuda_bf16.h>
#include <cstdint>
#include <math.h>

#define Bx 32
#define Dd 256
#define Kk 2048
#define Nn 32768
#define HWp 1024

#define Q_ELEMS   8388608
#define FULL_OUT  8421379
#define TAU       1e-4f

// ---- device scratch (no dynamic allocations allowed) ----
__device__ __nv_bfloat16 g_Xhi[Nn * Dd];    // 16.8 MB [N][D]
__device__ __nv_bfloat16 g_Xlo[Nn * Dd];    // 16.8 MB
__device__ __nv_bfloat16 g_BhiT[Dd * Kk];   // 1 MB [D][K] normalized hi
__device__ __nv_bfloat16 g_BloT[Dd * Kk];   // 1 MB
__device__ float g_Ef[Kk * Dd];             // 2 MB [K][D] normalized fp32 (rescue)
__device__ float g_inv[Kk];
__device__ int   g_idx[Nn];
__device__ int   g_hist[Kk];
__device__ float g_part[1024];
__device__ int   g_rcnt;
__device__ int   g_rlist[Nn];

// ======================= PTX helpers (compute_80+ baseline) ================
__device__ __forceinline__ uint32_t smem_u32(const void* p) {
    uint32_t a;
    asm("{ .reg .u64 t; cvta.to.shared.u64 t, %1; cvt.u32.u64 %0, t; }" : "=r"(a) : "l"(p));
    return a;
}
__device__ __forceinline__ void ldsm_x4(uint32_t* r, uint32_t addr) {
    asm volatile("ldmatrix.sync.aligned.m8n8.x4.shared.b16 {%0,%1,%2,%3}, [%4];"
        : "=r"(r[0]), "=r"(r[1]), "=r"(r[2]), "=r"(r[3]) : "r"(addr));
}
__device__ __forceinline__ void ldsm_x4_t(uint32_t* r, uint32_t addr) {
    asm volatile("ldmatrix.sync.aligned.m8n8.x4.trans.shared.b16 {%0,%1,%2,%3}, [%4];"
        : "=r"(r[0]), "=r"(r[1]), "=r"(r[2]), "=r"(r[3]) : "r"(addr));
}
__device__ __forceinline__ void mma_bf16(float* c, const uint32_t* a, const uint32_t* b) {
    asm("mma.sync.aligned.m16n8k16.row.col.f32.bf16.bf16.f32 "
        "{%0,%1,%2,%3}, {%4,%5,%6,%7}, {%8,%9}, {%0,%1,%2,%3};"
        : "+f"(c[0]), "+f"(c[1]), "+f"(c[2]), "+f"(c[3])
        : "r"(a[0]), "r"(a[1]), "r"(a[2]), "r"(a[3]), "r"(b[0]), "r"(b[1]));
}
__device__ __forceinline__ void cp_async16(uint32_t dst, const void* src) {
    asm volatile("cp.async.cg.shared.global [%0], [%1], 16;" :: "r"(dst), "l"(src) : "memory");
}
#define CP_COMMIT() asm volatile("cp.async.commit_group;" ::: "memory")
#define CP_WAIT0()  asm volatile("cp.async.wait_group 0;" ::: "memory")

// ---------------------------------------------------------------------------
// Kernel 1: per-column inverse norms + zero histogram + reset rescue count
// ---------------------------------------------------------------------------
__global__ void k_invnorm(const float* __restrict__ E) {
    int k = blockIdx.x * blockDim.x + threadIdx.x;
    float ss = 0.f;
#pragma unroll 8
    for (int d = 0; d < Dd; ++d) { float v = E[d * Kk + k]; ss = fmaf(v, v, ss); }
    g_inv[k] = 1.0f / fmaxf(sqrtf(ss), 1e-12f);
    g_hist[k] = 0;
    if (k == 0) g_rcnt = 0;
}

// ---------------------------------------------------------------------------
// Kernel 2: transpose+split X: [B,D,H,W] fp32 -> Xhi/Xlo [N,D] bf16 row-major
// ---------------------------------------------------------------------------
__global__ __launch_bounds__(256) void k_prepx(const float* __restrict__ x) {
    __shared__ float t[64][65];
    const int tid = threadIdx.x;
    const int hw0 = blockIdx.x * 64, d0 = blockIdx.y * 64, b = blockIdx.z;
    const float* xb = x + ((size_t)b * Dd + d0) * HWp + hw0;
#pragma unroll
    for (int i = 0; i < 16; ++i) {
        int idx = i * 256 + tid, di = idx >> 6, hwi = idx & 63;
        t[di][hwi] = xb[(size_t)di * HWp + hwi];
    }
    __syncthreads();
    const int n0 = b * HWp + hw0;
#pragma unroll
    for (int i = 0; i < 8; ++i) {
        int idx = i * 256 + tid;
        int hwi = idx >> 5;
        int di = (idx & 31) * 2;
        float v0 = t[di][hwi], v1 = t[di + 1][hwi];
        __nv_bfloat16 h0 = __float2bfloat16(v0);
        __nv_bfloat16 h1 = __float2bfloat16(v1);
        __nv_bfloat16 l0 = __float2bfloat16(v0 - __bfloat162float(h0));
        __nv_bfloat16 l1 = __float2bfloat16(v1 - __bfloat162float(h1));
        size_t o = (size_t)(n0 + hwi) * Dd + d0 + di;
        __nv_bfloat162 hh; hh.x = h0; hh.y = h1;
        __nv_bfloat162 ll; ll.x = l0; ll.y = l1;
        *reinterpret_cast<__nv_bfloat162*>(&g_Xhi[o]) = hh;
        *reinterpret_cast<__nv_bfloat162*>(&g_Xlo[o]) = ll;
    }
}

// ---------------------------------------------------------------------------
// Kernel 3: codebook prep: E [D,K] -> g_Ef [K][D] fp32 normalized,
//           g_BhiT/g_BloT [D][K] bf16 split
// ---------------------------------------------------------------------------
__global__ __launch_bounds__(256) void k_prepe(const float* __restrict__ E) {
    __shared__ float t[64][65];
    const int tid = threadIdx.x;
    const int k0 = blockIdx.x * 64, d0 = blockIdx.y * 64;
#pragma unroll
    for (int i = 0; i < 16; ++i) {
        int idx = i * 256 + tid, di = idx >> 6, ki = idx & 63;
        t[di][ki] = E[(size_t)(d0 + di) * Kk + k0 + ki] * g_inv[k0 + ki];
    }
    __syncthreads();
#pragma unroll
    for (int i = 0; i < 16; ++i) {
        int idx = i * 256 + tid, ki = idx >> 6, di = idx & 63;
        g_Ef[(size_t)(k0 + ki) * Dd + d0 + di] = t[di][ki];
    }
#pragma unroll
    for (int i = 0; i < 8; ++i) {
        int idx = i * 256 + tid;
        int di = idx >> 5;
        int ki = (idx & 31) * 2;
        float v0 = t[di][ki], v1 = t[di][ki + 1];
        __nv_bfloat16 h0 = __float2bfloat16(v0);
        __nv_bfloat16 h1 = __float2bfloat16(v1);
        float l0 = v0 - __bfloat162float(h0);
        float l1 = v1 - __bfloat162float(h1);
        size_t o = (size_t)(d0 + di) * Kk + k0 + ki;
        __nv_bfloat162 hh; hh.x = h0; hh.y = h1;
        __nv_bfloat162 ll; ll.x = __float2bfloat16(l0); ll.y = __float2bfloat16(l1);
        *reinterpret_cast<__nv_bfloat162*>(&g_BhiT[o]) = hh;
        *reinterpret_cast<__nv_bfloat162*>(&g_BloT[o]) = ll;
    }
}

// ---------------------------------------------------------------------------
// Kernel 4: warp-MMA split-3 bf16 GEMM + top-2 argmax (R8-proven structure,
// B staging upgraded to cp.async). CTA: 256 thr / 64 rows, A hi+lo resident
// (64KB, row-major swizzled, non-trans ldmatrix). 8 warps: wm=wid&1, wn=wid>>1.
// ---------------------------------------------------------------------------
#define SM_ALO 32768
#define SM_B   65536
#define SM_RED 98304
#define SM_TOT 101376

__global__ __launch_bounds__(256, 2) void k_mma_argmax() {
    extern __shared__ char sm[];
    const uint32_t sb = smem_u32(sm);
    const int tid = threadIdx.x;
    const int lane = tid & 31;
    const int wid = tid >> 5;
    const int wm = wid & 1, wn = wid >> 1;
    const int rbase = blockIdx.x * 64;
    const int ldr = tid >> 4, ldu = tid & 15;

    // ---- kick off B chunk 0 (ct=0,kc=0) into stage 0 via cp.async ----
#pragma unroll
    for (int j = 0; j < 2; ++j) {
        int r = j * 16 + ldr;
        size_t so = ((size_t)r * Kk) * 2 + (size_t)ldu * 16;
        uint32_t dst = sb + SM_B + r * 256 + ((ldu ^ (r & 7)) << 4);
        cp_async16(dst, (const char*)g_BhiT + so);
        cp_async16(dst + 8192, (const char*)g_BloT + so);
    }
    CP_COMMIT();

    // ---- load A (both splits) into swizzled SMEM: row stride 512B ----
#pragma unroll
    for (int s = 0; s < 2; ++s) {
        const __nv_bfloat16* src = s ? g_Xlo : g_Xhi;
#pragma unroll
        for (int i = 0; i < 8; ++i) {
            int idx = i * 256 + tid;       // 2048 uint4
            int r = idx >> 5, u = idx & 31;
            uint4 v = *(const uint4*)(src + (size_t)(rbase + r) * Dd + u * 8);
            *(uint4*)(sm + s * SM_ALO + r * 512 + ((u ^ (r & 7)) << 4)) = v;
        }
    }
    CP_WAIT0();
    __syncthreads();

    float c[2][4][4];
#pragma unroll
    for (int mi = 0; mi < 2; ++mi)
#pragma unroll
        for (int j = 0; j < 4; ++j)
#pragma unroll
            for (int q = 0; q < 4; ++q) c[mi][j][q] = 0.f;

    float v1[4], v2[4];
    int   i1[4];
#pragma unroll
    for (int s = 0; s < 4; ++s) { v1[s] = -3.0e38f; v2[s] = -3.0e38f; i1[s] = 0; }

    int stage = 0;
    const int kk = (lane & 7) + ((lane >> 3) & 1) * 8;

    for (int cid = 0; cid < 128; ++cid) {
        const int ct = cid >> 3, kc = cid & 7;

        // issue next chunk's cp.async into the other stage
        if (cid < 127) {
            int nct = (cid + 1) >> 3, nkc = (cid + 1) & 7;
#pragma unroll
            for (int j = 0; j < 2; ++j) {
                int r = j * 16 + ldr;
                size_t so = ((size_t)(nkc * 32 + r) * Kk + nct * 128) * 2 + (size_t)ldu * 16;
                uint32_t dst = sb + SM_B + (stage ^ 1) * 16384 + r * 256 + ((ldu ^ (r & 7)) << 4);
                cp_async16(dst, (const char*)g_BhiT + so);
                cp_async16(dst + 8192, (const char*)g_BloT + so);
            }
        }
        CP_COMMIT();

        // ---- two k16 sub-chunks (R8-proven A path: non-trans ldmatrix) ----
#pragma unroll
        for (int kcs = 0; kcs < 2; ++kcs) {
            uint32_t ah[2][4], al[2][4];
#pragma unroll
            for (int mi = 0; mi < 2; ++mi) {
                int r0 = wm * 32 + mi * 16 + (lane & 15);
                int u0 = kc * 4 + kcs * 2 + (lane >> 4);
                uint32_t aaddr = sb + r0 * 512 + ((u0 ^ (r0 & 7)) << 4);
                ldsm_x4(ah[mi], aaddr);
                ldsm_x4(al[mi], aaddr + SM_ALO);
            }
            uint32_t bh[2][4], bl[2][4];
            const uint32_t bbase = sb + SM_B + stage * 16384 + kcs * 4096;
#pragma unroll
            for (int p = 0; p < 2; ++p) {
                int u0 = wn * 4 + p * 2 + (lane >> 4);
                uint32_t baddr = bbase + kk * 256 + ((u0 ^ (kk & 7)) << 4);
                ldsm_x4_t(bh[p], baddr);
                ldsm_x4_t(bl[p], baddr + 8192);
            }
            // ---- 24 HMMA: hi*hi + hi*lo + lo*hi ----
#pragma unroll
            for (int mi = 0; mi < 2; ++mi)
#pragma unroll
                for (int p = 0; p < 2; ++p) {
                    mma_bf16(c[mi][2 * p],     ah[mi], &bh[p][0]);
                    mma_bf16(c[mi][2 * p + 1], ah[mi], &bh[p][2]);
                    mma_bf16(c[mi][2 * p],     ah[mi], &bl[p][0]);
                    mma_bf16(c[mi][2 * p + 1], ah[mi], &bl[p][2]);
                    mma_bf16(c[mi][2 * p],     al[mi], &bh[p][0]);
                    mma_bf16(c[mi][2 * p + 1], al[mi], &bh[p][2]);
                }
        }

        // ---- column-tile epilogue: fold accumulators into running top-2 ----
        if (kc == 7) {
            const int cb = ct * 128 + wn * 32 + (lane & 3) * 2;
#pragma unroll
            for (int mi = 0; mi < 2; ++mi)
#pragma unroll
                for (int j = 0; j < 4; ++j)
#pragma unroll
                    for (int q = 0; q < 4; ++q) {
                        float v = c[mi][j][q];
                        int col = cb + j * 8 + (q & 1);
                        int slot = mi * 2 + (q >> 1);
                        if (v > v1[slot]) { v2[slot] = v1[slot]; v1[slot] = v; i1[slot] = col; }
                        else if (v > v2[slot]) { v2[slot] = v; }
                        c[mi][j][q] = 0.f;
                    }
        }

        CP_WAIT0();
        __syncthreads();
        stage ^= 1;
    }

    // ---- cross-lane merge over the 4 lanes sharing a row ----
#pragma unroll
    for (int s = 0; s < 4; ++s) {
#pragma unroll
        for (int m = 1; m <= 2; m <<= 1) {
            float ov1 = __shfl_xor_sync(0xffffffffu, v1[s], m);
            float ov2 = __shfl_xor_sync(0xffffffffu, v2[s], m);
            int   oi1 = __shfl_xor_sync(0xffffffffu, i1[s], m);
            if (ov1 > v1[s]) { v2[s] = fmaxf(v1[s], ov2); v1[s] = ov1; i1[s] = oi1; }
            else             { v2[s] = fmaxf(v2[s], ov1); }
        }
    }
    float* sv1 = (float*)(sm + SM_RED);
    float* sv2 = (float*)(sm + SM_RED + 1024);
    int*   si1 = (int*)  (sm + SM_RED + 2048);
    if ((lane & 3) == 0) {
#pragma unroll
        for (int s = 0; s < 4; ++s) {
            int row = wm * 32 + (s >> 1) * 16 + (s & 1) * 8 + (lane >> 2);
            sv1[row * 4 + wn] = v1[s];
            sv2[row * 4 + wn] = v2[s];
            si1[row * 4 + wn] = i1[s];
        }
    }
    __syncthreads();
    if (tid < 64) {
        float t1 = -3.0e38f, t2 = -3.0e38f;
        int ti = 0;
#pragma unroll
        for (int p = 0; p < 4; ++p) {
            float a1 = sv1[tid * 4 + p], a2 = sv2[tid * 4 + p];
            int ai = si1[tid * 4 + p];
            if (a1 > t1) { t2 = fmaxf(t1, a2); t1 = a1; ti = ai; }
            else         { t2 = fmaxf(t2, a1); }
        }
        g_idx[rbase + tid] = ti;
        if (t1 - t2 < TAU) {
            int p = atomicAdd(&g_rcnt, 1);
            g_rlist[p] = rbase + tid;
        }
    }
}

// ---------------------------------------------------------------------------
// Kernel 5: exact fp32 rescue for rows with small top1-top2 gap.
// ---------------------------------------------------------------------------
__global__ __launch_bounds__(256) void k_rescue(const float* __restrict__ x) {
    __shared__ float sx[8][257];
    __shared__ int   srows[8];
    __shared__ float rv[256];
    __shared__ int   ri[256];
    const int tid = threadIdx.x;
    const int total = g_rcnt;

    for (int t0 = blockIdx.x * 8; t0 < total; t0 += gridDim.x * 8) {
        const int m = min(8, total - t0);
        if (tid < 8) srows[tid] = (tid < m) ? g_rlist[t0 + tid] : 0;
        __syncthreads();
        for (int j = 0; j < 8; ++j) {
            int n = srows[j];
            int b = n >> 10, hw = n & 1023;
            sx[j][tid] = (j < m) ? x[((size_t)b * Dd + tid) * HWp + hw] : 0.f;
        }
        __syncthreads();

        float bv[8]; int bi[8];
#pragma unroll
        for (int j = 0; j < 8; ++j) { bv[j] = -3.0e38f; bi[j] = 0; }
        for (int s = 0; s < 8; ++s) {
            int k = s * 256 + tid;
            const float* er = g_Ef + (size_t)k * Dd;
            float dot[8];
#pragma unroll
            for (int j = 0; j < 8; ++j) dot[j] = 0.f;
            for (int d = 0; d < Dd; d += 4) {
                float4 e = *(const float4*)(er + d);
#pragma unroll
                for (int j = 0; j < 8; ++j) {
                    dot[j] = fmaf(sx[j][d], e.x, dot[j]);
                    dot[j] = fmaf(sx[j][d + 1], e.y, dot[j]);
                    dot[j] = fmaf(sx[j][d + 2], e.z, dot[j]);
                    dot[j] = fmaf(sx[j][d + 3], e.w, dot[j]);
                }
            }
#pragma unroll
            for (int j = 0; j < 8; ++j)
                if (dot[j] > bv[j]) { bv[j] = dot[j]; bi[j] = k; }
        }
        for (int j = 0; j < 8; ++j) {
            rv[tid] = bv[j]; ri[tid] = bi[j];
            __syncthreads();
            for (int s2 = 128; s2 > 0; s2 >>= 1) {
                if (tid < s2) {
                    if (rv[tid + s2] > rv[tid] ||
                        (rv[tid + s2] == rv[tid] && ri[tid + s2] < ri[tid])) {
                        rv[tid] = rv[tid + s2]; ri[tid] = ri[tid + s2];
                    }
                }
                __syncthreads();
            }
            if (tid == 0 && j < m) g_idx[srows[j]] = ri[0];
            __syncthreads();
        }
    }
}

// ---------------------------------------------------------------------------
// Kernel 6: gather + fused MSE partials + histogram + index output (8-way D split)
// ---------------------------------------------------------------------------
__global__ void k_gather(const float* __restrict__ x, const float* __restrict__ E,
                         float* __restrict__ out, int extras) {
    __shared__ float red[256];
    const int tid = threadIdx.x;
    const int n = blockIdx.x * 256 + tid;
    const int q = blockIdx.y;
    const int d0 = q * 32;
    const int idx = g_idx[n];
    const int b = n >> 10;
    const int hw = n & 1023;

    const float* xb = x + ((size_t)b * Dd + d0) * HWp + hw;
    float* ob = out + ((size_t)b * Dd + d0) * HWp + hw;

    float acc = 0.f;
#pragma unroll 4
    for (int d = 0; d < 32; ++d) {
        float qv = E[(d0 + d) * Kk + idx];
        float xv = xb[(size_t)d * HWp];
        ob[(size_t)d * HWp] = qv;
        float df = xv - qv;
        acc = fmaf(df, df, acc);
    }
    if (q == 0) {
        atomicAdd(&g_hist[idx], 1);
        if (extras) out[Q_ELEMS + 3 + n] = (float)idx;
    }

    red[tid] = acc;
    __syncthreads();
    for (int s = 128; s > 0; s >>= 1) {
        if (tid < s) red[tid] += red[tid + s];
        __syncthreads();
    }
    if (tid == 0) g_part[blockIdx.x * 8 + q] = red[0];
}

// ---------------------------------------------------------------------------
// Kernel 7: finalize scalars
// ---------------------------------------------------------------------------
__global__ void k_final(float* __restrict__ out, int extras) {
    __shared__ float red[256];
    const int tid = threadIdx.x;

    red[tid] = g_part[tid] + g_part[tid + 256] + g_part[tid + 512] + g_part[tid + 768];
    __syncthreads();
    for (int s = 128; s > 0; s >>= 1) {
        if (tid < s) red[tid] += red[tid + s];
        __syncthreads();
    }
    float mse = red[0] / (float)Q_ELEMS;
    __syncthreads();

    float e = 0.f;
    for (int bin = tid; bin < Kk; bin += 256) {
        float p = (float)g_hist[bin] / (float)Nn;
        e += p * logf(p + 1e-10f);
    }
    red[tid] = e;
    __syncthreads();
    for (int s = 128; s > 0; s >>= 1) {
        if (tid < s) red[tid] += red[tid + s];
        __syncthreads();
    }
    if (tid == 0 && extras) {
        out[Q_ELEMS + 0] = mse;
        out[Q_ELEMS + 1] = mse;
        out[Q_ELEMS + 2] = red[0];
    }
}

// ---------------------------------------------------------------------------
extern "C" void kernel_launch(void* const* d_in, const int* in_sizes, int n_in,
                              void* d_out, int out_size) {
    const float* x = (const float*)d_in[0];   // [32,256,32,32]
    const float* E = (const float*)d_in[1];   // [256,2048]
    float* out = (float*)d_out;
    const int extras = (out_size >= FULL_OUT) ? 1 : 0;

    k_invnorm<<<Kk / 256, 256>>>(E);
    k_prepx<<<dim3(HWp / 64, Dd / 64, Bx), 256>>>(x);
    k_prepe<<<dim3(Kk / 64, Dd / 64), 256>>>(E);

    cudaFuncSetAttribute(k_mma_argmax,
                         cudaFuncAttributeMaxDynamicSharedMemorySize, SM_TOT);
    k_mma_argmax<<<Nn / 64, 256, SM_TOT>>>();

    k_rescue<<<256, 256>>>(x);
    k_gather<<<dim3(Nn / 256, 8), 256>>>(x, E, out, extras);
    k_final<<<1, 256>>>(out, extras);
}

// round 11
// speedup vs baseline: 1.5687x; 1.0171x over previous
#include <cuda_runtime.h>
#include <cuda_bf16.h>
#include <cstdint>
#include <math.h>

#define Bx 32
#define Dd 256
#define Kk 2048
#define Nn 32768
#define HWp 1024

#define Q_ELEMS   8388608
#define FULL_OUT  8421379
#define TAU       1e-4f

// ---- device scratch (no dynamic allocations allowed) ----
__device__ __nv_bfloat16 g_BhiT[Dd * Kk];   // 1 MB [D][K] normalized hi
__device__ __nv_bfloat16 g_BloT[Dd * Kk];   // 1 MB
__device__ float g_Ef[Kk * Dd];             // 2 MB [K][D] normalized fp32 (rescue)
__device__ float g_inv[Kk];
__device__ int   g_idx[Nn];
__device__ int   g_hist[Kk];
__device__ float g_part[256];
__device__ int   g_rcnt;
__device__ int   g_rlist[Nn];

// ======================= PTX helpers (compute_80+ baseline) ================
__device__ __forceinline__ uint32_t smem_u32(const void* p) {
    uint32_t a;
    asm("{ .reg .u64 t; cvta.to.shared.u64 t, %1; cvt.u32.u64 %0, t; }" : "=r"(a) : "l"(p));
    return a;
}
__device__ __forceinline__ void ldsm_x4(uint32_t* r, uint32_t addr) {
    asm volatile("ldmatrix.sync.aligned.m8n8.x4.shared.b16 {%0,%1,%2,%3}, [%4];"
        : "=r"(r[0]), "=r"(r[1]), "=r"(r[2]), "=r"(r[3]) : "r"(addr));
}
__device__ __forceinline__ void ldsm_x4_t(uint32_t* r, uint32_t addr) {
    asm volatile("ldmatrix.sync.aligned.m8n8.x4.trans.shared.b16 {%0,%1,%2,%3}, [%4];"
        : "=r"(r[0]), "=r"(r[1]), "=r"(r[2]), "=r"(r[3]) : "r"(addr));
}
__device__ __forceinline__ void mma_bf16(float* c, const uint32_t* a, const uint32_t* b) {
    asm("mma.sync.aligned.m16n8k16.row.col.f32.bf16.bf16.f32 "
        "{%0,%1,%2,%3}, {%4,%5,%6,%7}, {%8,%9}, {%0,%1,%2,%3};"
        : "+f"(c[0]), "+f"(c[1]), "+f"(c[2]), "+f"(c[3])
        : "r"(a[0]), "r"(a[1]), "r"(a[2]), "r"(a[3]), "r"(b[0]), "r"(b[1]));
}
__device__ __forceinline__ void cp_async16(uint32_t dst, const void* src) {
    asm volatile("cp.async.cg.shared.global [%0], [%1], 16;" :: "r"(dst), "l"(src) : "memory");
}
#define CP_COMMIT() asm volatile("cp.async.commit_group;" ::: "memory")
#define CP_WAIT0()  asm volatile("cp.async.wait_group 0;" ::: "memory")

// ---------------------------------------------------------------------------
// Kernel 1: per-column inverse norms + zero histogram + reset rescue count
// ---------------------------------------------------------------------------
__global__ void k_invnorm(const float* __restrict__ E) {
    int k = blockIdx.x * blockDim.x + threadIdx.x;
    float ss = 0.f;
#pragma unroll 8
    for (int d = 0; d < Dd; ++d) { float v = E[d * Kk + k]; ss = fmaf(v, v, ss); }
    g_inv[k] = 1.0f / fmaxf(sqrtf(ss), 1e-12f);
    g_hist[k] = 0;
    if (k == 0) g_rcnt = 0;
}

// ---------------------------------------------------------------------------
// Kernel 2: codebook prep: E [D,K] -> g_Ef [K][D] fp32 normalized,
//           g_BhiT/g_BloT [D][K] bf16 split
// ---------------------------------------------------------------------------
__global__ __launch_bounds__(256) void k_prepe(const float* __restrict__ E) {
    __shared__ float t[64][65];
    const int tid = threadIdx.x;
    const int k0 = blockIdx.x * 64, d0 = blockIdx.y * 64;
#pragma unroll
    for (int i = 0; i < 16; ++i) {
        int idx = i * 256 + tid, di = idx >> 6, ki = idx & 63;
        t[di][ki] = E[(size_t)(d0 + di) * Kk + k0 + ki] * g_inv[k0 + ki];
    }
    __syncthreads();
#pragma unroll
    for (int i = 0; i < 16; ++i) {
        int idx = i * 256 + tid, ki = idx >> 6, di = idx & 63;
        g_Ef[(size_t)(k0 + ki) * Dd + d0 + di] = t[di][ki];
    }
#pragma unroll
    for (int i = 0; i < 8; ++i) {
        int idx = i * 256 + tid;
        int di = idx >> 5;
        int ki = (idx & 31) * 2;
        float v0 = t[di][ki], v1 = t[di][ki + 1];
        __nv_bfloat16 h0 = __float2bfloat16(v0);
        __nv_bfloat16 h1 = __float2bfloat16(v1);
        float l0 = v0 - __bfloat162float(h0);
        float l1 = v1 - __bfloat162float(h1);
        size_t o = (size_t)(d0 + di) * Kk + k0 + ki;
        __nv_bfloat162 hh; hh.x = h0; hh.y = h1;
        __nv_bfloat162 ll; ll.x = __float2bfloat16(l0); ll.y = __float2bfloat16(l1);
        *reinterpret_cast<__nv_bfloat162*>(&g_BhiT[o]) = hh;
        *reinterpret_cast<__nv_bfloat162*>(&g_BloT[o]) = ll;
    }
}

// ---------------------------------------------------------------------------
// Kernel 3: warp-MMA split-3 bf16 GEMM + top-2 argmax.
// A built IN-CTA from raw x via fp32 smem-staging transpose (produces the
// exact swizzled A layout the proven non-trans ldmatrix path consumes).
// B streamed via cp.async double-buffered [k32][n128] stages.
// CTA: 256 thr / 64 rows; 8 warps: wm=wid&1, wn=wid>>1.
// ---------------------------------------------------------------------------
#define SM_ALO 32768
#define SM_B   65536
#define SM_RED 98304
#define SM_TOT 101376

__global__ __launch_bounds__(256, 2) void k_mma_argmax(const float* __restrict__ x) {
    extern __shared__ char sm[];
    const uint32_t sb = smem_u32(sm);
    const int tid = threadIdx.x;
    const int lane = tid & 31;
    const int wid = tid >> 5;
    const int wm = wid & 1, wn = wid >> 1;
    const int rbase = blockIdx.x * 64;
    const int b = rbase >> 10, hw0 = rbase & 1023;
    const int ldr = tid >> 4, ldu = tid & 15;

    // ---- build A (hi+lo, swizzled [row][d]) from raw x ----
    // staging: 128 d x 68 floats (pad 68: 16B-aligned float4, conflict-free
    // column reads) in the B region (dead until chunk 0 is issued below).
    {
        float* stg = (float*)(sm + SM_B);
#pragma unroll
        for (int h = 0; h < 2; ++h) {
            __syncthreads();   // staging reuse guard
#pragma unroll
            for (int i = 0; i < 8; ++i) {
                int idx = i * 256 + tid;
                int d = idx >> 4, r4 = idx & 15;
                float4 v = *(const float4*)(x + ((size_t)b * Dd + h * 128 + d) * HWp + hw0 + r4 * 4);
                *(float4*)&stg[d * 68 + r4 * 4] = v;
            }
            __syncthreads();
#pragma unroll
            for (int it = 0; it < 4; ++it) {
                int idx = it * 256 + tid;
                int r = idx & 63, u = idx >> 6;   // u 0..15
                float f[8];
#pragma unroll
                for (int j = 0; j < 8; ++j) f[j] = stg[(u * 8 + j) * 68 + r];
                uint32_t hi[4], lo[4];
#pragma unroll
                for (int q = 0; q < 4; ++q) {
                    __nv_bfloat16 h0 = __float2bfloat16(f[2 * q]);
                    __nv_bfloat16 h1 = __float2bfloat16(f[2 * q + 1]);
                    __nv_bfloat162 hh; hh.x = h0; hh.y = h1;
                    hi[q] = *reinterpret_cast<uint32_t*>(&hh);
                    __nv_bfloat162 llp;
                    llp.x = __float2bfloat16(f[2 * q] - __bfloat162float(h0));
                    llp.y = __float2bfloat16(f[2 * q + 1] - __bfloat162float(h1));
                    lo[q] = *reinterpret_cast<uint32_t*>(&llp);
                }
                int ug = h * 16 + u;               // 0..31 over full D
                uint32_t ad = r * 512 + ((ug ^ (r & 7)) << 4);
                *(uint4*)(sm + ad) = make_uint4(hi[0], hi[1], hi[2], hi[3]);
                *(uint4*)(sm + SM_ALO + ad) = make_uint4(lo[0], lo[1], lo[2], lo[3]);
            }
        }
        __syncthreads();   // A complete; staging dead -> B region free
    }

    // ---- kick off B chunk 0 (ct=0,kc=0) into stage 0 via cp.async ----
#pragma unroll
    for (int j = 0; j < 2; ++j) {
        int r = j * 16 + ldr;
        size_t so = ((size_t)r * Kk) * 2 + (size_t)ldu * 16;
        uint32_t dst = sb + SM_B + r * 256 + ((ldu ^ (r & 7)) << 4);
        cp_async16(dst, (const char*)g_BhiT + so);
        cp_async16(dst + 8192, (const char*)g_BloT + so);
    }
    CP_COMMIT();
    CP_WAIT0();
    __syncthreads();

    float c[2][4][4];
#pragma unroll
    for (int mi = 0; mi < 2; ++mi)
#pragma unroll
        for (int j = 0; j < 4; ++j)
#pragma unroll
            for (int q = 0; q < 4; ++q) c[mi][j][q] = 0.f;

    float v1[4], v2[4];
    int   i1[4];
#pragma unroll
    for (int s = 0; s < 4; ++s) { v1[s] = -3.0e38f; v2[s] = -3.0e38f; i1[s] = 0; }

    int stage = 0;
    const int kk = (lane & 7) + ((lane >> 3) & 1) * 8;

    for (int cid = 0; cid < 128; ++cid) {
        const int ct = cid >> 3, kc = cid & 7;

        // issue next chunk's cp.async into the other stage
        if (cid < 127) {
            int nct = (cid + 1) >> 3, nkc = (cid + 1) & 7;
#pragma unroll
            for (int j = 0; j < 2; ++j) {
                int r = j * 16 + ldr;
                size_t so = ((size_t)(nkc * 32 + r) * Kk + nct * 128) * 2 + (size_t)ldu * 16;
                uint32_t dst = sb + SM_B + (stage ^ 1) * 16384 + r * 256 + ((ldu ^ (r & 7)) << 4);
                cp_async16(dst, (const char*)g_BhiT + so);
                cp_async16(dst + 8192, (const char*)g_BloT + so);
            }
        }
        CP_COMMIT();

        // ---- two k16 sub-chunks (proven non-trans ldmatrix A path) ----
#pragma unroll
        for (int kcs = 0; kcs < 2; ++kcs) {
            uint32_t ah[2][4], al[2][4];
#pragma unroll
            for (int mi = 0; mi < 2; ++mi) {
                int r0 = wm * 32 + mi * 16 + (lane & 15);
                int u0 = kc * 4 + kcs * 2 + (lane >> 4);
                uint32_t aaddr = sb + r0 * 512 + ((u0 ^ (r0 & 7)) << 4);
                ldsm_x4(ah[mi], aaddr);
                ldsm_x4(al[mi], aaddr + SM_ALO);
            }
            uint32_t bh[2][4], bl[2][4];
            const uint32_t bbase = sb + SM_B + stage * 16384 + kcs * 4096;
#pragma unroll
            for (int p = 0; p < 2; ++p) {
                int u0 = wn * 4 + p * 2 + (lane >> 4);
                uint32_t baddr = bbase + kk * 256 + ((u0 ^ (kk & 7)) << 4);
                ldsm_x4_t(bh[p], baddr);
                ldsm_x4_t(bl[p], baddr + 8192);
            }
            // ---- 24 HMMA: hi*hi + hi*lo + lo*hi ----
#pragma unroll
            for (int mi = 0; mi < 2; ++mi)
#pragma unroll
                for (int p = 0; p < 2; ++p) {
                    mma_bf16(c[mi][2 * p],     ah[mi], &bh[p][0]);
                    mma_bf16(c[mi][2 * p + 1], ah[mi], &bh[p][2]);
                    mma_bf16(c[mi][2 * p],     ah[mi], &bl[p][0]);
                    mma_bf16(c[mi][2 * p + 1], ah[mi], &bl[p][2]);
                    mma_bf16(c[mi][2 * p],     al[mi], &bh[p][0]);
                    mma_bf16(c[mi][2 * p + 1], al[mi], &bh[p][2]);
                }
        }

        // ---- column-tile epilogue: fold accumulators into running top-2 ----
        if (kc == 7) {
            const int cb = ct * 128 + wn * 32 + (lane & 3) * 2;
#pragma unroll
            for (int mi = 0; mi < 2; ++mi)
#pragma unroll
                for (int j = 0; j < 4; ++j)
#pragma unroll
                    for (int q = 0; q < 4; ++q) {
                        float v = c[mi][j][q];
                        int col = cb + j * 8 + (q & 1);
                        int slot = mi * 2 + (q >> 1);
                        if (v > v1[slot]) { v2[slot] = v1[slot]; v1[slot] = v; i1[slot] = col; }
                        else if (v > v2[slot]) { v2[slot] = v; }
                        c[mi][j][q] = 0.f;
                    }
        }

        CP_WAIT0();
        __syncthreads();
        stage ^= 1;
    }

    // ---- cross-lane merge over the 4 lanes sharing a row ----
#pragma unroll
    for (int s = 0; s < 4; ++s) {
#pragma unroll
        for (int m = 1; m <= 2; m <<= 1) {
            float ov1 = __shfl_xor_sync(0xffffffffu, v1[s], m);
            float ov2 = __shfl_xor_sync(0xffffffffu, v2[s], m);
            int   oi1 = __shfl_xor_sync(0xffffffffu, i1[s], m);
            if (ov1 > v1[s]) { v2[s] = fmaxf(v1[s], ov2); v1[s] = ov1; i1[s] = oi1; }
            else             { v2[s] = fmaxf(v2[s], ov1); }
        }
    }
    float* sv1 = (float*)(sm + SM_RED);
    float* sv2 = (float*)(sm + SM_RED + 1024);
    int*   si1 = (int*)  (sm + SM_RED + 2048);
    if ((lane & 3) == 0) {
#pragma unroll
        for (int s = 0; s < 4; ++s) {
            int row = wm * 32 + (s >> 1) * 16 + (s & 1) * 8 + (lane >> 2);
            sv1[row * 4 + wn] = v1[s];
            sv2[row * 4 + wn] = v2[s];
            si1[row * 4 + wn] = i1[s];
        }
    }
    __syncthreads();
    if (tid < 64) {
        float t1 = -3.0e38f, t2 = -3.0e38f;
        int ti = 0;
#pragma unroll
        for (int p = 0; p < 4; ++p) {
            float a1 = sv1[tid * 4 + p], a2 = sv2[tid * 4 + p];
            int ai = si1[tid * 4 + p];
            if (a1 > t1) { t2 = fmaxf(t1, a2); t1 = a1; ti = ai; }
            else         { t2 = fmaxf(t2, a1); }
        }
        g_idx[rbase + tid] = ti;
        if (t1 - t2 < TAU) {
            int p = atomicAdd(&g_rcnt, 1);
            g_rlist[p] = rbase + tid;
        }
    }
}

// ---------------------------------------------------------------------------
// Kernel 4: exact fp32 rescue for rows with small top1-top2 gap.
// ---------------------------------------------------------------------------
__global__ __launch_bounds__(256) void k_rescue(const float* __restrict__ x) {
    __shared__ float sx[8][257];
    __shared__ int   srows[8];
    __shared__ float rv[256];
    __shared__ int   ri[256];
    const int tid = threadIdx.x;
    const int total = g_rcnt;

    for (int t0 = blockIdx.x * 8; t0 < total; t0 += gridDim.x * 8) {
        const int m = min(8, total - t0);
        if (tid < 8) srows[tid] = (tid < m) ? g_rlist[t0 + tid] : 0;
        __syncthreads();
        for (int j = 0; j < 8; ++j) {
            int n = srows[j];
            int b = n >> 10, hw = n & 1023;
            sx[j][tid] = (j < m) ? x[((size_t)b * Dd + tid) * HWp + hw] : 0.f;
        }
        __syncthreads();

        float bv[8]; int bi[8];
#pragma unroll
        for (int j = 0; j < 8; ++j) { bv[j] = -3.0e38f; bi[j] = 0; }
        for (int s = 0; s < 8; ++s) {
            int k = s * 256 + tid;
            const float* er = g_Ef + (size_t)k * Dd;
            float dot[8];
#pragma unroll
            for (int j = 0; j < 8; ++j) dot[j] = 0.f;
            for (int d = 0; d < Dd; d += 4) {
                float4 e = *(const float4*)(er + d);
#pragma unroll
                for (int j = 0; j < 8; ++j) {
                    dot[j] = fmaf(sx[j][d], e.x, dot[j]);
                    dot[j] = fmaf(sx[j][d + 1], e.y, dot[j]);
                    dot[j] = fmaf(sx[j][d + 2], e.z, dot[j]);
                    dot[j] = fmaf(sx[j][d + 3], e.w, dot[j]);
                }
            }
#pragma unroll
            for (int j = 0; j < 8; ++j)
                if (dot[j] > bv[j]) { bv[j] = dot[j]; bi[j] = k; }
        }
        for (int j = 0; j < 8; ++j) {
            rv[tid] = bv[j]; ri[tid] = bi[j];
            __syncthreads();
            for (int s2 = 128; s2 > 0; s2 >>= 1) {
                if (tid < s2) {
                    if (rv[tid + s2] > rv[tid] ||
                        (rv[tid + s2] == rv[tid] && ri[tid + s2] < ri[tid])) {
                        rv[tid] = rv[tid + s2]; ri[tid] = ri[tid + s2];
                    }
                }
                __syncthreads();
            }
            if (tid == 0 && j < m) g_idx[srows[j]] = ri[0];
            __syncthreads();
        }
    }
}

// ---------------------------------------------------------------------------
// Kernel 5: gather + fused MSE partials + histogram + index output.
// Thread owns 4 consecutive positions (float4 stream side); 8-way D split.
// ---------------------------------------------------------------------------
__global__ void k_gather(const float* __restrict__ x, const float* __restrict__ E,
                         float* __restrict__ out, int extras) {
    __shared__ float red[256];
    const int tid = threadIdx.x;
    const int n0 = blockIdx.x * 1024 + tid * 4;
    const int q = blockIdx.y;
    const int d0 = q * 32;
    const int4 idx4 = *(const int4*)&g_idx[n0];
    const int b = n0 >> 10;
    const int hw = n0 & 1023;

    const float* xb = x + ((size_t)b * Dd + d0) * HWp + hw;
    float* ob = out + ((size_t)b * Dd + d0) * HWp + hw;

    float acc = 0.f;
#pragma unroll 4
    for (int d = 0; d < 32; ++d) {
        const float* Er = E + (size_t)(d0 + d) * Kk;
        float4 xv = *(const float4*)&xb[(size_t)d * HWp];
        float4 qv = make_float4(Er[idx4.x], Er[idx4.y], Er[idx4.z], Er[idx4.w]);
        *(float4*)&ob[(size_t)d * HWp] = qv;
        float dx = xv.x - qv.x, dy = xv.y - qv.y;
        float dz = xv.z - qv.z, dw = xv.w - qv.w;
        acc = fmaf(dx, dx, acc); acc = fmaf(dy, dy, acc);
        acc = fmaf(dz, dz, acc); acc = fmaf(dw, dw, acc);
    }
    if (q == 0) {
        atomicAdd(&g_hist[idx4.x], 1);
        atomicAdd(&g_hist[idx4.y], 1);
        atomicAdd(&g_hist[idx4.z], 1);
        atomicAdd(&g_hist[idx4.w], 1);
        if (extras) {
            out[Q_ELEMS + 3 + n0 + 0] = (float)idx4.x;
            out[Q_ELEMS + 3 + n0 + 1] = (float)idx4.y;
            out[Q_ELEMS + 3 + n0 + 2] = (float)idx4.z;
            out[Q_ELEMS + 3 + n0 + 3] = (float)idx4.w;
        }
    }

    red[tid] = acc;
    __syncthreads();
    for (int s = 128; s > 0; s >>= 1) {
        if (tid < s) red[tid] += red[tid + s];
        __syncthreads();
    }
    if (tid == 0) g_part[blockIdx.x * 8 + q] = red[0];
}

// ---------------------------------------------------------------------------
// Kernel 6: finalize scalars
// ---------------------------------------------------------------------------
__global__ void k_final(float* __restrict__ out, int extras) {
    __shared__ float red[256];
    const int tid = threadIdx.x;

    red[tid] = g_part[tid];
    __syncthreads();
    for (int s = 128; s > 0; s >>= 1) {
        if (tid < s) red[tid] += red[tid + s];
        __syncthreads();
    }
    float mse = red[0] / (float)Q_ELEMS;
    __syncthreads();

    float e = 0.f;
    for (int bin = tid; bin < Kk; bin += 256) {
        float p = (float)g_hist[bin] / (float)Nn;
        e += p * logf(p + 1e-10f);
    }
    red[tid] = e;
    __syncthreads();
    for (int s = 128; s > 0; s >>= 1) {
        if (tid < s) red[tid] += red[tid + s];
        __syncthreads();
    }
    if (tid == 0 && extras) {
        out[Q_ELEMS + 0] = mse;
        out[Q_ELEMS + 1] = mse;
        out[Q_ELEMS + 2] = red[0];
    }
}

// ---------------------------------------------------------------------------
extern "C" void kernel_launch(void* const* d_in, const int* in_sizes, int n_in,
                              void* d_out, int out_size) {
    const float* x = (const float*)d_in[0];   // [32,256,32,32]
    const float* E = (const float*)d_in[1];   // [256,2048]
    float* out = (float*)d_out;
    const int extras = (out_size >= FULL_OUT) ? 1 : 0;

    k_invnorm<<<Kk / 256, 256>>>(E);
    k_prepe<<<dim3(Kk / 64, Dd / 64), 256>>>(E);

    cudaFuncSetAttribute(k_mma_argmax,
                         cudaFuncAttributeMaxDynamicSharedMemorySize, SM_TOT);
    k_mma_argmax<<<Nn / 64, 256, SM_TOT>>>(x);

    k_rescue<<<256, 256>>>(x);
    k_gather<<<dim3(Nn / 1024, 8), 256>>>(x, E, out, extras);
    k_final<<<1, 256>>>(out, extras);
}

// round 12
// speedup vs baseline: 2.1055x; 1.3422x over previous
#include <cuda_runtime.h>
#include <cuda_bf16.h>
#include <cstdint>
#include <math.h>

#define Bx 32
#define Dd 256
#define Kk 2048
#define Nn 32768
#define HWp 1024

#define Q_ELEMS   8388608
#define FULL_OUT  8421379
#define TAU       1e-4f

// ---- device scratch (no dynamic allocations allowed) ----
__device__ __nv_bfloat16 g_BhiT[Dd * Kk];   // 1 MB [D][K] normalized hi
__device__ __nv_bfloat16 g_BloT[Dd * Kk];   // 1 MB
__device__ float g_EfT[Dd * Kk];            // 2 MB [D][K] normalized fp32 (rescue)
__device__ float g_inv[Kk];
__device__ int   g_idx[Nn];
__device__ int   g_hist[Kk];
__device__ float g_part[256];
__device__ int   g_rcnt;
__device__ int   g_rlist[Nn];

// ======================= PTX helpers (compute_80+ baseline) ================
__device__ __forceinline__ uint32_t smem_u32(const void* p) {
    uint32_t a;
    asm("{ .reg .u64 t; cvta.to.shared.u64 t, %1; cvt.u32.u64 %0, t; }" : "=r"(a) : "l"(p));
    return a;
}
__device__ __forceinline__ void ldsm_x4(uint32_t* r, uint32_t addr) {
    asm volatile("ldmatrix.sync.aligned.m8n8.x4.shared.b16 {%0,%1,%2,%3}, [%4];"
        : "=r"(r[0]), "=r"(r[1]), "=r"(r[2]), "=r"(r[3]) : "r"(addr));
}
__device__ __forceinline__ void ldsm_x4_t(uint32_t* r, uint32_t addr) {
    asm volatile("ldmatrix.sync.aligned.m8n8.x4.trans.shared.b16 {%0,%1,%2,%3}, [%4];"
        : "=r"(r[0]), "=r"(r[1]), "=r"(r[2]), "=r"(r[3]) : "r"(addr));
}
__device__ __forceinline__ void mma_bf16(float* c, const uint32_t* a, const uint32_t* b) {
    asm("mma.sync.aligned.m16n8k16.row.col.f32.bf16.bf16.f32 "
        "{%0,%1,%2,%3}, {%4,%5,%6,%7}, {%8,%9}, {%0,%1,%2,%3};"
        : "+f"(c[0]), "+f"(c[1]), "+f"(c[2]), "+f"(c[3])
        : "r"(a[0]), "r"(a[1]), "r"(a[2]), "r"(a[3]), "r"(b[0]), "r"(b[1]));
}
__device__ __forceinline__ void cp_async16(uint32_t dst, const void* src) {
    asm volatile("cp.async.cg.shared.global [%0], [%1], 16;" :: "r"(dst), "l"(src) : "memory");
}
#define CP_COMMIT() asm volatile("cp.async.commit_group;" ::: "memory")
#define CP_WAIT0()  asm volatile("cp.async.wait_group 0;" ::: "memory")

// ---------------------------------------------------------------------------
// Kernel 1: per-column inverse norms + zero histogram + reset rescue count
// ---------------------------------------------------------------------------
__global__ void k_invnorm(const float* __restrict__ E) {
    int k = blockIdx.x * blockDim.x + threadIdx.x;
    float ss = 0.f;
#pragma unroll 8
    for (int d = 0; d < Dd; ++d) { float v = E[d * Kk + k]; ss = fmaf(v, v, ss); }
    g_inv[k] = 1.0f / fmaxf(sqrtf(ss), 1e-12f);
    g_hist[k] = 0;
    if (k == 0) g_rcnt = 0;
}

// ---------------------------------------------------------------------------
// Kernel 2: codebook prep: E [D,K] -> g_EfT [D][K] fp32 normalized (coalesced),
//           g_BhiT/g_BloT [D][K] bf16 split
// ---------------------------------------------------------------------------
__global__ __launch_bounds__(256) void k_prepe(const float* __restrict__ E) {
    __shared__ float t[64][65];
    const int tid = threadIdx.x;
    const int k0 = blockIdx.x * 64, d0 = blockIdx.y * 64;
#pragma unroll
    for (int i = 0; i < 16; ++i) {
        int idx = i * 256 + tid, di = idx >> 6, ki = idx & 63;
        t[di][ki] = E[(size_t)(d0 + di) * Kk + k0 + ki] * g_inv[k0 + ki];
    }
    __syncthreads();
    // [D][K] fp32 rescue table (coalesced over ki)
#pragma unroll
    for (int i = 0; i < 16; ++i) {
        int idx = i * 256 + tid, di = idx >> 6, ki = idx & 63;
        g_EfT[(size_t)(d0 + di) * Kk + k0 + ki] = t[di][ki];
    }
    // [D][K] bf16 hi/lo, two K at a time
#pragma unroll
    for (int i = 0; i < 8; ++i) {
        int idx = i * 256 + tid;
        int di = idx >> 5;
        int ki = (idx & 31) * 2;
        float v0 = t[di][ki], v1 = t[di][ki + 1];
        __nv_bfloat16 h0 = __float2bfloat16(v0);
        __nv_bfloat16 h1 = __float2bfloat16(v1);
        float l0 = v0 - __bfloat162float(h0);
        float l1 = v1 - __bfloat162float(h1);
        size_t o = (size_t)(d0 + di) * Kk + k0 + ki;
        __nv_bfloat162 hh; hh.x = h0; hh.y = h1;
        __nv_bfloat162 ll; ll.x = __float2bfloat16(l0); ll.y = __float2bfloat16(l1);
        *reinterpret_cast<__nv_bfloat162*>(&g_BhiT[o]) = hh;
        *reinterpret_cast<__nv_bfloat162*>(&g_BloT[o]) = ll;
    }
}

// ---------------------------------------------------------------------------
// Kernel 3: warp-MMA split-3 bf16 GEMM + top-2 argmax (unchanged from R11).
// ---------------------------------------------------------------------------
#define SM_ALO 32768
#define SM_B   65536
#define SM_RED 98304
#define SM_TOT 101376

__global__ __launch_bounds__(256, 2) void k_mma_argmax(const float* __restrict__ x) {
    extern __shared__ char sm[];
    const uint32_t sb = smem_u32(sm);
    const int tid = threadIdx.x;
    const int lane = tid & 31;
    const int wid = tid >> 5;
    const int wm = wid & 1, wn = wid >> 1;
    const int rbase = blockIdx.x * 64;
    const int b = rbase >> 10, hw0 = rbase & 1023;
    const int ldr = tid >> 4, ldu = tid & 15;

    // ---- build A (hi+lo, swizzled [row][d]) from raw x ----
    {
        float* stg = (float*)(sm + SM_B);
#pragma unroll
        for (int h = 0; h < 2; ++h) {
            __syncthreads();
#pragma unroll
            for (int i = 0; i < 8; ++i) {
                int idx = i * 256 + tid;
                int d = idx >> 4, r4 = idx & 15;
                float4 v = *(const float4*)(x + ((size_t)b * Dd + h * 128 + d) * HWp + hw0 + r4 * 4);
                *(float4*)&stg[d * 68 + r4 * 4] = v;
            }
            __syncthreads();
#pragma unroll
            for (int it = 0; it < 4; ++it) {
                int idx = it * 256 + tid;
                int r = idx & 63, u = idx >> 6;
                float f[8];
#pragma unroll
                for (int j = 0; j < 8; ++j) f[j] = stg[(u * 8 + j) * 68 + r];
                uint32_t hi[4], lo[4];
#pragma unroll
                for (int q = 0; q < 4; ++q) {
                    __nv_bfloat16 h0 = __float2bfloat16(f[2 * q]);
                    __nv_bfloat16 h1 = __float2bfloat16(f[2 * q + 1]);
                    __nv_bfloat162 hh; hh.x = h0; hh.y = h1;
                    hi[q] = *reinterpret_cast<uint32_t*>(&hh);
                    __nv_bfloat162 llp;
                    llp.x = __float2bfloat16(f[2 * q] - __bfloat162float(h0));
                    llp.y = __float2bfloat16(f[2 * q + 1] - __bfloat162float(h1));
                    lo[q] = *reinterpret_cast<uint32_t*>(&llp);
                }
                int ug = h * 16 + u;
                uint32_t ad = r * 512 + ((ug ^ (r & 7)) << 4);
                *(uint4*)(sm + ad) = make_uint4(hi[0], hi[1], hi[2], hi[3]);
                *(uint4*)(sm + SM_ALO + ad) = make_uint4(lo[0], lo[1], lo[2], lo[3]);
            }
        }
        __syncthreads();
    }

    // ---- kick off B chunk 0 into stage 0 ----
#pragma unroll
    for (int j = 0; j < 2; ++j) {
        int r = j * 16 + ldr;
        size_t so = ((size_t)r * Kk) * 2 + (size_t)ldu * 16;
        uint32_t dst = sb + SM_B + r * 256 + ((ldu ^ (r & 7)) << 4);
        cp_async16(dst, (const char*)g_BhiT + so);
        cp_async16(dst + 8192, (const char*)g_BloT + so);
    }
    CP_COMMIT();
    CP_WAIT0();
    __syncthreads();

    float c[2][4][4];
#pragma unroll
    for (int mi = 0; mi < 2; ++mi)
#pragma unroll
        for (int j = 0; j < 4; ++j)
#pragma unroll
            for (int q = 0; q < 4; ++q) c[mi][j][q] = 0.f;

    float v1[4], v2[4];
    int   i1[4];
#pragma unroll
    for (int s = 0; s < 4; ++s) { v1[s] = -3.0e38f; v2[s] = -3.0e38f; i1[s] = 0; }

    int stage = 0;
    const int kk = (lane & 7) + ((lane >> 3) & 1) * 8;

    for (int cid = 0; cid < 128; ++cid) {
        const int ct = cid >> 3, kc = cid & 7;

        if (cid < 127) {
            int nct = (cid + 1) >> 3, nkc = (cid + 1) & 7;
#pragma unroll
            for (int j = 0; j < 2; ++j) {
                int r = j * 16 + ldr;
                size_t so = ((size_t)(nkc * 32 + r) * Kk + nct * 128) * 2 + (size_t)ldu * 16;
                uint32_t dst = sb + SM_B + (stage ^ 1) * 16384 + r * 256 + ((ldu ^ (r & 7)) << 4);
                cp_async16(dst, (const char*)g_BhiT + so);
                cp_async16(dst + 8192, (const char*)g_BloT + so);
            }
        }
        CP_COMMIT();

#pragma unroll
        for (int kcs = 0; kcs < 2; ++kcs) {
            uint32_t ah[2][4], al[2][4];
#pragma unroll
            for (int mi = 0; mi < 2; ++mi) {
                int r0 = wm * 32 + mi * 16 + (lane & 15);
                int u0 = kc * 4 + kcs * 2 + (lane >> 4);
                uint32_t aaddr = sb + r0 * 512 + ((u0 ^ (r0 & 7)) << 4);
                ldsm_x4(ah[mi], aaddr);
                ldsm_x4(al[mi], aaddr + SM_ALO);
            }
            uint32_t bh[2][4], bl[2][4];
            const uint32_t bbase = sb + SM_B + stage * 16384 + kcs * 4096;
#pragma unroll
            for (int p = 0; p < 2; ++p) {
                int u0 = wn * 4 + p * 2 + (lane >> 4);
                uint32_t baddr = bbase + kk * 256 + ((u0 ^ (kk & 7)) << 4);
                ldsm_x4_t(bh[p], baddr);
                ldsm_x4_t(bl[p], baddr + 8192);
            }
#pragma unroll
            for (int mi = 0; mi < 2; ++mi)
#pragma unroll
                for (int p = 0; p < 2; ++p) {
                    mma_bf16(c[mi][2 * p],     ah[mi], &bh[p][0]);
                    mma_bf16(c[mi][2 * p + 1], ah[mi], &bh[p][2]);
                    mma_bf16(c[mi][2 * p],     ah[mi], &bl[p][0]);
                    mma_bf16(c[mi][2 * p + 1], ah[mi], &bl[p][2]);
                    mma_bf16(c[mi][2 * p],     al[mi], &bh[p][0]);
                    mma_bf16(c[mi][2 * p + 1], al[mi], &bh[p][2]);
                }
        }

        if (kc == 7) {
            const int cb = ct * 128 + wn * 32 + (lane & 3) * 2;
#pragma unroll
            for (int mi = 0; mi < 2; ++mi)
#pragma unroll
                for (int j = 0; j < 4; ++j)
#pragma unroll
                    for (int q = 0; q < 4; ++q) {
                        float v = c[mi][j][q];
                        int col = cb + j * 8 + (q & 1);
                        int slot = mi * 2 + (q >> 1);
                        if (v > v1[slot]) { v2[slot] = v1[slot]; v1[slot] = v; i1[slot] = col; }
                        else if (v > v2[slot]) { v2[slot] = v; }
                        c[mi][j][q] = 0.f;
                    }
        }

        CP_WAIT0();
        __syncthreads();
        stage ^= 1;
    }

#pragma unroll
    for (int s = 0; s < 4; ++s) {
#pragma unroll
        for (int m = 1; m <= 2; m <<= 1) {
            float ov1 = __shfl_xor_sync(0xffffffffu, v1[s], m);
            float ov2 = __shfl_xor_sync(0xffffffffu, v2[s], m);
            int   oi1 = __shfl_xor_sync(0xffffffffu, i1[s], m);
            if (ov1 > v1[s]) { v2[s] = fmaxf(v1[s], ov2); v1[s] = ov1; i1[s] = oi1; }
            else             { v2[s] = fmaxf(v2[s], ov1); }
        }
    }
    float* sv1 = (float*)(sm + SM_RED);
    float* sv2 = (float*)(sm + SM_RED + 1024);
    int*   si1 = (int*)  (sm + SM_RED + 2048);
    if ((lane & 3) == 0) {
#pragma unroll
        for (int s = 0; s < 4; ++s) {
            int row = wm * 32 + (s >> 1) * 16 + (s & 1) * 8 + (lane >> 2);
            sv1[row * 4 + wn] = v1[s];
            sv2[row * 4 + wn] = v2[s];
            si1[row * 4 + wn] = i1[s];
        }
    }
    __syncthreads();
    if (tid < 64) {
        float t1 = -3.0e38f, t2 = -3.0e38f;
        int ti = 0;
#pragma unroll
        for (int p = 0; p < 4; ++p) {
            float a1 = sv1[tid * 4 + p], a2 = sv2[tid * 4 + p];
            int ai = si1[tid * 4 + p];
            if (a1 > t1) { t2 = fmaxf(t1, a2); t1 = a1; ti = ai; }
            else         { t2 = fmaxf(t2, a1); }
        }
        g_idx[rbase + tid] = ti;
        if (t1 - t2 < TAU) {
            int p = atomicAdd(&g_rcnt, 1);
            g_rlist[p] = rbase + tid;
        }
    }
}

// ---------------------------------------------------------------------------
// Kernel 4: exact fp32 rescue — ONE BLOCK PER ROW, coalesced g_EfT streams.
// Thread owns codes tid*4+{0..3} and 1024+tid*4+{0..3}.
// ---------------------------------------------------------------------------
__global__ __launch_bounds__(256) void k_rescue(const float* __restrict__ x) {
    __shared__ float sx[256];
    __shared__ float rv[256];
    __shared__ int   ri[256];
    const int tid = threadIdx.x;
    const int total = g_rcnt;

    for (int t = blockIdx.x; t < total; t += gridDim.x) {
        const int n = g_rlist[t];
        const int b = n >> 10, hw = n & 1023;
        __syncthreads();                               // sx/rv reuse guard
        sx[tid] = x[((size_t)b * Dd + tid) * HWp + hw];
        __syncthreads();

        float acc[8];
#pragma unroll
        for (int c = 0; c < 8; ++c) acc[c] = 0.f;
        const int k0 = tid * 4;
        for (int d = 0; d < Dd; ++d) {
            float xd = sx[d];
            float4 e0 = *(const float4*)&g_EfT[(size_t)d * Kk + k0];
            float4 e1 = *(const float4*)&g_EfT[(size_t)d * Kk + 1024 + k0];
            acc[0] = fmaf(xd, e0.x, acc[0]); acc[1] = fmaf(xd, e0.y, acc[1]);
            acc[2] = fmaf(xd, e0.z, acc[2]); acc[3] = fmaf(xd, e0.w, acc[3]);
            acc[4] = fmaf(xd, e1.x, acc[4]); acc[5] = fmaf(xd, e1.y, acc[5]);
            acc[6] = fmaf(xd, e1.z, acc[6]); acc[7] = fmaf(xd, e1.w, acc[7]);
        }
        // in-thread best (ascending k order: strict > keeps smallest index)
        float bv = acc[0]; int bi = k0;
#pragma unroll
        for (int c = 1; c < 4; ++c)
            if (acc[c] > bv) { bv = acc[c]; bi = k0 + c; }
#pragma unroll
        for (int c = 0; c < 4; ++c)
            if (acc[4 + c] > bv) { bv = acc[4 + c]; bi = 1024 + k0 + c; }

        rv[tid] = bv; ri[tid] = bi;
        __syncthreads();
        for (int s = 128; s > 0; s >>= 1) {
            if (tid < s) {
                if (rv[tid + s] > rv[tid] ||
                    (rv[tid + s] == rv[tid] && ri[tid + s] < ri[tid])) {
                    rv[tid] = rv[tid + s]; ri[tid] = ri[tid + s];
                }
            }
            __syncthreads();
        }
        if (tid == 0) g_idx[n] = ri[0];
    }
}

// ---------------------------------------------------------------------------
// Kernel 5: gather + fused MSE partials + histogram + index output.
// ---------------------------------------------------------------------------
__global__ void k_gather(const float* __restrict__ x, const float* __restrict__ E,
                         float* __restrict__ out, int extras) {
    __shared__ float red[256];
    const int tid = threadIdx.x;
    const int n0 = blockIdx.x * 1024 + tid * 4;
    const int q = blockIdx.y;
    const int d0 = q * 32;
    const int4 idx4 = *(const int4*)&g_idx[n0];
    const int b = n0 >> 10;
    const int hw = n0 & 1023;

    const float* xb = x + ((size_t)b * Dd + d0) * HWp + hw;
    float* ob = out + ((size_t)b * Dd + d0) * HWp + hw;

    float acc = 0.f;
#pragma unroll 4
    for (int d = 0; d < 32; ++d) {
        const float* Er = E + (size_t)(d0 + d) * Kk;
        float4 xv = *(const float4*)&xb[(size_t)d * HWp];
        float4 qv = make_float4(Er[idx4.x], Er[idx4.y], Er[idx4.z], Er[idx4.w]);
        *(float4*)&ob[(size_t)d * HWp] = qv;
        float dx = xv.x - qv.x, dy = xv.y - qv.y;
        float dz = xv.z - qv.z, dw = xv.w - qv.w;
        acc = fmaf(dx, dx, acc); acc = fmaf(dy, dy, acc);
        acc = fmaf(dz, dz, acc); acc = fmaf(dw, dw, acc);
    }
    if (q == 0) {
        atomicAdd(&g_hist[idx4.x], 1);
        atomicAdd(&g_hist[idx4.y], 1);
        atomicAdd(&g_hist[idx4.z], 1);
        atomicAdd(&g_hist[idx4.w], 1);
        if (extras) {
            out[Q_ELEMS + 3 + n0 + 0] = (float)idx4.x;
            out[Q_ELEMS + 3 + n0 + 1] = (float)idx4.y;
            out[Q_ELEMS + 3 + n0 + 2] = (float)idx4.z;
            out[Q_ELEMS + 3 + n0 + 3] = (float)idx4.w;
        }
    }

    red[tid] = acc;
    __syncthreads();
    for (int s = 128; s > 0; s >>= 1) {
        if (tid < s) red[tid] += red[tid + s];
        __syncthreads();
    }
    if (tid == 0) g_part[blockIdx.x * 8 + q] = red[0];
}

// ---------------------------------------------------------------------------
// Kernel 6: finalize scalars
// ---------------------------------------------------------------------------
__global__ void k_final(float* __restrict__ out, int extras) {
    __shared__ float red[256];
    const int tid = threadIdx.x;

    red[tid] = g_part[tid];
    __syncthreads();
    for (int s = 128; s > 0; s >>= 1) {
        if (tid < s) red[tid] += red[tid + s];
        __syncthreads();
    }
    float mse = red[0] / (float)Q_ELEMS;
    __syncthreads();

    float e = 0.f;
    for (int bin = tid; bin < Kk; bin += 256) {
        float p = (float)g_hist[bin] / (float)Nn;
        e += p * logf(p + 1e-10f);
    }
    red[tid] = e;
    __syncthreads();
    for (int s = 128; s > 0; s >>= 1) {
        if (tid < s) red[tid] += red[tid + s];
        __syncthreads();
    }
    if (tid == 0 && extras) {
        out[Q_ELEMS + 0] = mse;
        out[Q_ELEMS + 1] = mse;
        out[Q_ELEMS + 2] = red[0];
    }
}

// ---------------------------------------------------------------------------
extern "C" void kernel_launch(void* const* d_in, const int* in_sizes, int n_in,
                              void* d_out, int out_size) {
    const float* x = (const float*)d_in[0];   // [32,256,32,32]
    const float* E = (const float*)d_in[1];   // [256,2048]
    float* out = (float*)d_out;
    const int extras = (out_size >= FULL_OUT) ? 1 : 0;

    k_invnorm<<<Kk / 256, 256>>>(E);
    k_prepe<<<dim3(Kk / 64, Dd / 64), 256>>>(E);

    cudaFuncSetAttribute(k_mma_argmax,
                         cudaFuncAttributeMaxDynamicSharedMemorySize, SM_TOT);
    k_mma_argmax<<<Nn / 64, 256, SM_TOT>>>(x);

    k_rescue<<<256, 256>>>(x);
    k_gather<<<dim3(Nn / 1024, 8), 256>>>(x, E, out, extras);
    k_final<<<1, 256>>>(out, extras);
}

// round 13
// speedup vs baseline: 2.2526x; 1.0698x over previous
#include <cuda_runtime.h>
#include <cuda_bf16.h>
#include <cstdint>
#include <math.h>

#define Bx 32
#define Dd 256
#define Kk 2048
#define Nn 32768
#define HWp 1024

#define Q_ELEMS   8388608
#define FULL_OUT  8421379
#define TAU       1e-4f

// ---- device scratch (no dynamic allocations allowed) ----
__device__ __nv_bfloat16 g_BhiT[Dd * Kk];   // 1 MB [D][K] normalized hi
__device__ __nv_bfloat16 g_BloT[Dd * Kk];   // 1 MB
__device__ float g_EfT[Dd * Kk];            // 2 MB [D][K] normalized fp32 (rescue)
__device__ float g_inv[Kk];
__device__ int   g_idx[Nn];
__device__ int   g_hist[Kk];
__device__ float g_part[256];
__device__ int   g_rcnt;
__device__ int   g_rlist[Nn];
__device__ unsigned long long g_best[Nn];   // packed (sortable score | 2047-idx)

// ======================= PTX helpers (compute_80+ baseline) ================
__device__ __forceinline__ uint32_t smem_u32(const void* p) {
    uint32_t a;
    asm("{ .reg .u64 t; cvta.to.shared.u64 t, %1; cvt.u32.u64 %0, t; }" : "=r"(a) : "l"(p));
    return a;
}
__device__ __forceinline__ void ldsm_x4(uint32_t* r, uint32_t addr) {
    asm volatile("ldmatrix.sync.aligned.m8n8.x4.shared.b16 {%0,%1,%2,%3}, [%4];"
        : "=r"(r[0]), "=r"(r[1]), "=r"(r[2]), "=r"(r[3]) : "r"(addr));
}
__device__ __forceinline__ void ldsm_x4_t(uint32_t* r, uint32_t addr) {
    asm volatile("ldmatrix.sync.aligned.m8n8.x4.trans.shared.b16 {%0,%1,%2,%3}, [%4];"
        : "=r"(r[0]), "=r"(r[1]), "=r"(r[2]), "=r"(r[3]) : "r"(addr));
}
__device__ __forceinline__ void mma_bf16(float* c, const uint32_t* a, const uint32_t* b) {
    asm("mma.sync.aligned.m16n8k16.row.col.f32.bf16.bf16.f32 "
        "{%0,%1,%2,%3}, {%4,%5,%6,%7}, {%8,%9}, {%0,%1,%2,%3};"
        : "+f"(c[0]), "+f"(c[1]), "+f"(c[2]), "+f"(c[3])
        : "r"(a[0]), "r"(a[1]), "r"(a[2]), "r"(a[3]), "r"(b[0]), "r"(b[1]));
}
__device__ __forceinline__ void cp_async16(uint32_t dst, const void* src) {
    asm volatile("cp.async.cg.shared.global [%0], [%1], 16;" :: "r"(dst), "l"(src) : "memory");
}
#define CP_COMMIT() asm volatile("cp.async.commit_group;" ::: "memory")
#define CP_WAIT0()  asm volatile("cp.async.wait_group 0;" ::: "memory")

__device__ __forceinline__ uint32_t f32_sortable(float f) {
    uint32_t b = __float_as_uint(f);
    return (b & 0x80000000u) ? ~b : (b | 0x80000000u);
}

// ---------------------------------------------------------------------------
// Kernel 1: per-column inverse norms + zero histogram + reset rescue count
// ---------------------------------------------------------------------------
__global__ void k_invnorm(const float* __restrict__ E) {
    int k = blockIdx.x * blockDim.x + threadIdx.x;
    float ss = 0.f;
#pragma unroll 8
    for (int d = 0; d < Dd; ++d) { float v = E[d * Kk + k]; ss = fmaf(v, v, ss); }
    g_inv[k] = 1.0f / fmaxf(sqrtf(ss), 1e-12f);
    g_hist[k] = 0;
    if (k == 0) g_rcnt = 0;
}

// ---------------------------------------------------------------------------
// Kernel 2: codebook prep: E [D,K] -> g_EfT [D][K] fp32 normalized (coalesced),
//           g_BhiT/g_BloT [D][K] bf16 split
// ---------------------------------------------------------------------------
__global__ __launch_bounds__(256) void k_prepe(const float* __restrict__ E) {
    __shared__ float t[64][65];
    const int tid = threadIdx.x;
    const int k0 = blockIdx.x * 64, d0 = blockIdx.y * 64;
#pragma unroll
    for (int i = 0; i < 16; ++i) {
        int idx = i * 256 + tid, di = idx >> 6, ki = idx & 63;
        t[di][ki] = E[(size_t)(d0 + di) * Kk + k0 + ki] * g_inv[k0 + ki];
    }
    __syncthreads();
#pragma unroll
    for (int i = 0; i < 16; ++i) {
        int idx = i * 256 + tid, di = idx >> 6, ki = idx & 63;
        g_EfT[(size_t)(d0 + di) * Kk + k0 + ki] = t[di][ki];
    }
#pragma unroll
    for (int i = 0; i < 8; ++i) {
        int idx = i * 256 + tid;
        int di = idx >> 5;
        int ki = (idx & 31) * 2;
        float v0 = t[di][ki], v1 = t[di][ki + 1];
        __nv_bfloat16 h0 = __float2bfloat16(v0);
        __nv_bfloat16 h1 = __float2bfloat16(v1);
        float l0 = v0 - __bfloat162float(h0);
        float l1 = v1 - __bfloat162float(h1);
        size_t o = (size_t)(d0 + di) * Kk + k0 + ki;
        __nv_bfloat162 hh; hh.x = h0; hh.y = h1;
        __nv_bfloat162 ll; ll.x = __float2bfloat16(l0); ll.y = __float2bfloat16(l1);
        *reinterpret_cast<__nv_bfloat162*>(&g_BhiT[o]) = hh;
        *reinterpret_cast<__nv_bfloat162*>(&g_BloT[o]) = ll;
    }
}

// ---------------------------------------------------------------------------
// Kernel 3: warp-MMA split-3 bf16 GEMM + top-2 argmax (unchanged from R12,
// except flagged rows also reset g_best[n]).
// ---------------------------------------------------------------------------
#define SM_ALO 32768
#define SM_B   65536
#define SM_RED 98304
#define SM_TOT 101376

__global__ __launch_bounds__(256, 2) void k_mma_argmax(const float* __restrict__ x) {
    extern __shared__ char sm[];
    const uint32_t sb = smem_u32(sm);
    const int tid = threadIdx.x;
    const int lane = tid & 31;
    const int wid = tid >> 5;
    const int wm = wid & 1, wn = wid >> 1;
    const int rbase = blockIdx.x * 64;
    const int b = rbase >> 10, hw0 = rbase & 1023;
    const int ldr = tid >> 4, ldu = tid & 15;

    // ---- build A (hi+lo, swizzled [row][d]) from raw x ----
    {
        float* stg = (float*)(sm + SM_B);
#pragma unroll
        for (int h = 0; h < 2; ++h) {
            __syncthreads();
#pragma unroll
            for (int i = 0; i < 8; ++i) {
                int idx = i * 256 + tid;
                int d = idx >> 4, r4 = idx & 15;
                float4 v = *(const float4*)(x + ((size_t)b * Dd + h * 128 + d) * HWp + hw0 + r4 * 4);
                *(float4*)&stg[d * 68 + r4 * 4] = v;
            }
            __syncthreads();
#pragma unroll
            for (int it = 0; it < 4; ++it) {
                int idx = it * 256 + tid;
                int r = idx & 63, u = idx >> 6;
                float f[8];
#pragma unroll
                for (int j = 0; j < 8; ++j) f[j] = stg[(u * 8 + j) * 68 + r];
                uint32_t hi[4], lo[4];
#pragma unroll
                for (int q = 0; q < 4; ++q) {
                    __nv_bfloat16 h0 = __float2bfloat16(f[2 * q]);
                    __nv_bfloat16 h1 = __float2bfloat16(f[2 * q + 1]);
                    __nv_bfloat162 hh; hh.x = h0; hh.y = h1;
                    hi[q] = *reinterpret_cast<uint32_t*>(&hh);
                    __nv_bfloat162 llp;
                    llp.x = __float2bfloat16(f[2 * q] - __bfloat162float(h0));
                    llp.y = __float2bfloat16(f[2 * q + 1] - __bfloat162float(h1));
                    lo[q] = *reinterpret_cast<uint32_t*>(&llp);
                }
                int ug = h * 16 + u;
                uint32_t ad = r * 512 + ((ug ^ (r & 7)) << 4);
                *(uint4*)(sm + ad) = make_uint4(hi[0], hi[1], hi[2], hi[3]);
                *(uint4*)(sm + SM_ALO + ad) = make_uint4(lo[0], lo[1], lo[2], lo[3]);
            }
        }
        __syncthreads();
    }

    // ---- kick off B chunk 0 into stage 0 ----
#pragma unroll
    for (int j = 0; j < 2; ++j) {
        int r = j * 16 + ldr;
        size_t so = ((size_t)r * Kk) * 2 + (size_t)ldu * 16;
        uint32_t dst = sb + SM_B + r * 256 + ((ldu ^ (r & 7)) << 4);
        cp_async16(dst, (const char*)g_BhiT + so);
        cp_async16(dst + 8192, (const char*)g_BloT + so);
    }
    CP_COMMIT();
    CP_WAIT0();
    __syncthreads();

    float c[2][4][4];
#pragma unroll
    for (int mi = 0; mi < 2; ++mi)
#pragma unroll
        for (int j = 0; j < 4; ++j)
#pragma unroll
            for (int q = 0; q < 4; ++q) c[mi][j][q] = 0.f;

    float v1[4], v2[4];
    int   i1[4];
#pragma unroll
    for (int s = 0; s < 4; ++s) { v1[s] = -3.0e38f; v2[s] = -3.0e38f; i1[s] = 0; }

    int stage = 0;
    const int kk = (lane & 7) + ((lane >> 3) & 1) * 8;

    for (int cid = 0; cid < 128; ++cid) {
        const int ct = cid >> 3, kc = cid & 7;

        if (cid < 127) {
            int nct = (cid + 1) >> 3, nkc = (cid + 1) & 7;
#pragma unroll
            for (int j = 0; j < 2; ++j) {
                int r = j * 16 + ldr;
                size_t so = ((size_t)(nkc * 32 + r) * Kk + nct * 128) * 2 + (size_t)ldu * 16;
                uint32_t dst = sb + SM_B + (stage ^ 1) * 16384 + r * 256 + ((ldu ^ (r & 7)) << 4);
                cp_async16(dst, (const char*)g_BhiT + so);
                cp_async16(dst + 8192, (const char*)g_BloT + so);
            }
        }
        CP_COMMIT();

#pragma unroll
        for (int kcs = 0; kcs < 2; ++kcs) {
            uint32_t ah[2][4], al[2][4];
#pragma unroll
            for (int mi = 0; mi < 2; ++mi) {
                int r0 = wm * 32 + mi * 16 + (lane & 15);
                int u0 = kc * 4 + kcs * 2 + (lane >> 4);
                uint32_t aaddr = sb + r0 * 512 + ((u0 ^ (r0 & 7)) << 4);
                ldsm_x4(ah[mi], aaddr);
                ldsm_x4(al[mi], aaddr + SM_ALO);
            }
            uint32_t bh[2][4], bl[2][4];
            const uint32_t bbase = sb + SM_B + stage * 16384 + kcs * 4096;
#pragma unroll
            for (int p = 0; p < 2; ++p) {
                int u0 = wn * 4 + p * 2 + (lane >> 4);
                uint32_t baddr = bbase + kk * 256 + ((u0 ^ (kk & 7)) << 4);
                ldsm_x4_t(bh[p], baddr);
                ldsm_x4_t(bl[p], baddr + 8192);
            }
#pragma unroll
            for (int mi = 0; mi < 2; ++mi)
#pragma unroll
                for (int p = 0; p < 2; ++p) {
                    mma_bf16(c[mi][2 * p],     ah[mi], &bh[p][0]);
                    mma_bf16(c[mi][2 * p + 1], ah[mi], &bh[p][2]);
                    mma_bf16(c[mi][2 * p],     ah[mi], &bl[p][0]);
                    mma_bf16(c[mi][2 * p + 1], ah[mi], &bl[p][2]);
                    mma_bf16(c[mi][2 * p],     al[mi], &bh[p][0]);
                    mma_bf16(c[mi][2 * p + 1], al[mi], &bh[p][2]);
                }
        }

        if (kc == 7) {
            const int cb = ct * 128 + wn * 32 + (lane & 3) * 2;
#pragma unroll
            for (int mi = 0; mi < 2; ++mi)
#pragma unroll
                for (int j = 0; j < 4; ++j)
#pragma unroll
                    for (int q = 0; q < 4; ++q) {
                        float v = c[mi][j][q];
                        int col = cb + j * 8 + (q & 1);
                        int slot = mi * 2 + (q >> 1);
                        if (v > v1[slot]) { v2[slot] = v1[slot]; v1[slot] = v; i1[slot] = col; }
                        else if (v > v2[slot]) { v2[slot] = v; }
                        c[mi][j][q] = 0.f;
                    }
        }

        CP_WAIT0();
        __syncthreads();
        stage ^= 1;
    }

#pragma unroll
    for (int s = 0; s < 4; ++s) {
#pragma unroll
        for (int m = 1; m <= 2; m <<= 1) {
            float ov1 = __shfl_xor_sync(0xffffffffu, v1[s], m);
            float ov2 = __shfl_xor_sync(0xffffffffu, v2[s], m);
            int   oi1 = __shfl_xor_sync(0xffffffffu, i1[s], m);
            if (ov1 > v1[s]) { v2[s] = fmaxf(v1[s], ov2); v1[s] = ov1; i1[s] = oi1; }
            else             { v2[s] = fmaxf(v2[s], ov1); }
        }
    }
    float* sv1 = (float*)(sm + SM_RED);
    float* sv2 = (float*)(sm + SM_RED + 1024);
    int*   si1 = (int*)  (sm + SM_RED + 2048);
    if ((lane & 3) == 0) {
#pragma unroll
        for (int s = 0; s < 4; ++s) {
            int row = wm * 32 + (s >> 1) * 16 + (s & 1) * 8 + (lane >> 2);
            sv1[row * 4 + wn] = v1[s];
            sv2[row * 4 + wn] = v2[s];
            si1[row * 4 + wn] = i1[s];
        }
    }
    __syncthreads();
    if (tid < 64) {
        float t1 = -3.0e38f, t2 = -3.0e38f;
        int ti = 0;
#pragma unroll
        for (int p = 0; p < 4; ++p) {
            float a1 = sv1[tid * 4 + p], a2 = sv2[tid * 4 + p];
            int ai = si1[tid * 4 + p];
            if (a1 > t1) { t2 = fmaxf(t1, a2); t1 = a1; ti = ai; }
            else         { t2 = fmaxf(t2, a1); }
        }
        g_idx[rbase + tid] = ti;
        if (t1 - t2 < TAU) {
            g_best[rbase + tid] = 0ULL;          // floor for atomicMax keys
            int p = atomicAdd(&g_rcnt, 1);
            g_rlist[p] = rbase + tid;
        }
    }
}

// ---------------------------------------------------------------------------
// Kernel 4: exact fp32 rescue — each flagged row split across 8 partition
// blocks (256 codes / block, one code per thread, coalesced). Results merge
// via atomicMax on key = (sortable(score) << 32) | (2047 - idx).
// ---------------------------------------------------------------------------
__global__ __launch_bounds__(256) void k_rescue(const float* __restrict__ x) {
    __shared__ float sx[256];
    __shared__ float rv[256];
    __shared__ int   ri[256];
    const int tid = threadIdx.x;
    const int part = blockIdx.x & 7;
    const int total = g_rcnt;

    for (int t = blockIdx.x >> 3; t < total; t += 32) {
        const int n = g_rlist[t];
        const int b = n >> 10, hw = n & 1023;
        __syncthreads();                               // smem reuse guard
        sx[tid] = x[((size_t)b * Dd + tid) * HWp + hw];
        __syncthreads();

        const int k = part * 256 + tid;
        const float* col = g_EfT + k;
        float a0 = 0.f, a1 = 0.f, a2 = 0.f, a3 = 0.f;
#pragma unroll 8
        for (int d = 0; d < Dd; d += 4) {
            a0 = fmaf(sx[d],     col[(size_t)d * Kk],           a0);
            a1 = fmaf(sx[d + 1], col[(size_t)(d + 1) * Kk],     a1);
            a2 = fmaf(sx[d + 2], col[(size_t)(d + 2) * Kk],     a2);
            a3 = fmaf(sx[d + 3], col[(size_t)(d + 3) * Kk],     a3);
        }
        rv[tid] = (a0 + a1) + (a2 + a3);
        ri[tid] = k;
        __syncthreads();
        for (int s = 128; s > 0; s >>= 1) {
            if (tid < s) {
                if (rv[tid + s] > rv[tid] ||
                    (rv[tid + s] == rv[tid] && ri[tid + s] < ri[tid])) {
                    rv[tid] = rv[tid + s]; ri[tid] = ri[tid + s];
                }
            }
            __syncthreads();
        }
        if (tid == 0) {
            unsigned long long key =
                ((unsigned long long)f32_sortable(rv[0]) << 32) |
                (unsigned long long)(uint32_t)(2047 - ri[0]);
            atomicMax(&g_best[n], key);
        }
    }
}

// ---------------------------------------------------------------------------
// Kernel 5: unpack rescue winners into g_idx.
// ---------------------------------------------------------------------------
__global__ void k_pick() {
    const int total = g_rcnt;
    for (int t = threadIdx.x; t < total; t += 256) {
        int n = g_rlist[t];
        g_idx[n] = 2047 - (int)(uint32_t)(g_best[n] & 0xFFFFFFFFULL);
    }
}

// ---------------------------------------------------------------------------
// Kernel 6: gather + fused MSE partials + histogram + index output.
// ---------------------------------------------------------------------------
__global__ void k_gather(const float* __restrict__ x, const float* __restrict__ E,
                         float* __restrict__ out, int extras) {
    __shared__ float red[256];
    const int tid = threadIdx.x;
    const int n0 = blockIdx.x * 1024 + tid * 4;
    const int q = blockIdx.y;
    const int d0 = q * 32;
    const int4 idx4 = *(const int4*)&g_idx[n0];
    const int b = n0 >> 10;
    const int hw = n0 & 1023;

    const float* xb = x + ((size_t)b * Dd + d0) * HWp + hw;
    float* ob = out + ((size_t)b * Dd + d0) * HWp + hw;

    float acc = 0.f;
#pragma unroll 4
    for (int d = 0; d < 32; ++d) {
        const float* Er = E + (size_t)(d0 + d) * Kk;
        float4 xv = *(const float4*)&xb[(size_t)d * HWp];
        float4 qv = make_float4(Er[idx4.x], Er[idx4.y], Er[idx4.z], Er[idx4.w]);
        *(float4*)&ob[(size_t)d * HWp] = qv;
        float dx = xv.x - qv.x, dy = xv.y - qv.y;
        float dz = xv.z - qv.z, dw = xv.w - qv.w;
        acc = fmaf(dx, dx, acc); acc = fmaf(dy, dy, acc);
        acc = fmaf(dz, dz, acc); acc = fmaf(dw, dw, acc);
    }
    if (q == 0) {
        atomicAdd(&g_hist[idx4.x], 1);
        atomicAdd(&g_hist[idx4.y], 1);
        atomicAdd(&g_hist[idx4.z], 1);
        atomicAdd(&g_hist[idx4.w], 1);
        if (extras) {
            out[Q_ELEMS + 3 + n0 + 0] = (float)idx4.x;
            out[Q_ELEMS + 3 + n0 + 1] = (float)idx4.y;
            out[Q_ELEMS + 3 + n0 + 2] = (float)idx4.z;
            out[Q_ELEMS + 3 + n0 + 3] = (float)idx4.w;
        }
    }

    red[tid] = acc;
    __syncthreads();
    for (int s = 128; s > 0; s >>= 1) {
        if (tid < s) red[tid] += red[tid + s];
        __syncthreads();
    }
    if (tid == 0) g_part[blockIdx.x * 8 + q] = red[0];
}

// ---------------------------------------------------------------------------
// Kernel 7: finalize scalars
// ---------------------------------------------------------------------------
__global__ void k_final(float* __restrict__ out, int extras) {
    __shared__ float red[256];
    const int tid = threadIdx.x;

    red[tid] = g_part[tid];
    __syncthreads();
    for (int s = 128; s > 0; s >>= 1) {
        if (tid < s) red[tid] += red[tid + s];
        __syncthreads();
    }
    float mse = red[0] / (float)Q_ELEMS;
    __syncthreads();

    float e = 0.f;
    for (int bin = tid; bin < Kk; bin += 256) {
        float p = (float)g_hist[bin] / (float)Nn;
        e += p * logf(p + 1e-10f);
    }
    red[tid] = e;
    __syncthreads();
    for (int s = 128; s > 0; s >>= 1) {
        if (tid < s) red[tid] += red[tid + s];
        __syncthreads();
    }
    if (tid == 0 && extras) {
        out[Q_ELEMS + 0] = mse;
        out[Q_ELEMS + 1] = mse;
        out[Q_ELEMS + 2] = red[0];
    }
}

// ---------------------------------------------------------------------------
extern "C" void kernel_launch(void* const* d_in, const int* in_sizes, int n_in,
                              void* d_out, int out_size) {
    const float* x = (const float*)d_in[0];   // [32,256,32,32]
    const float* E = (const float*)d_in[1];   // [256,2048]
    float* out = (float*)d_out;
    const int extras = (out_size >= FULL_OUT) ? 1 : 0;

    k_invnorm<<<Kk / 256, 256>>>(E);
    k_prepe<<<dim3(Kk / 64, Dd / 64), 256>>>(E);

    cudaFuncSetAttribute(k_mma_argmax,
                         cudaFuncAttributeMaxDynamicSharedMemorySize, SM_TOT);
    k_mma_argmax<<<Nn / 64, 256, SM_TOT>>>(x);

    k_rescue<<<256, 256>>>(x);
    k_pick<<<1, 256>>>();
    k_gather<<<dim3(Nn / 1024, 8), 256>>>(x, E, out, extras);
    k_final<<<1, 256>>>(out, extras);
}